// round 1
// baseline (speedup 1.0000x reference)
#include <cuda_runtime.h>
#include <cstdint>

#define D_MODEL 1024
#define NHEAD   16
#define DK      64
#define BATCH   2
#define SEQ     2048
#define MTOT    (BATCH * SEQ)   // 4096

// Scratch (allocations are forbidden; __device__ globals are the sanctioned path)
__device__ float g_Q[MTOT * D_MODEL];
__device__ float g_K[MTOT * D_MODEL];
__device__ float g_V[MTOT * D_MODEL];
__device__ float g_O[MTOT * D_MODEL];

#define NEG_INF __int_as_float(0xff800000)

// ---------------------------------------------------------------------------
// C[m][n] = sum_k A[m][k] * B[n][k]   (A: MxK row-major, B: NxK row-major)
// 128x128 tile, BK=8, 256 threads, 8x8 per thread, double-buffered smem.
// ---------------------------------------------------------------------------
__global__ __launch_bounds__(256)
void sgemm_nt(const float* __restrict__ A, const float* __restrict__ B,
              float* __restrict__ C, int M, int N, int K)
{
    const int BM = 128, BN = 128, BK = 8;
    __shared__ float As[2][BK][BM];
    __shared__ float Bs[2][BK][BN];

    const int tid = threadIdx.x;
    const int bm = blockIdx.y * BM;
    const int bn = blockIdx.x * BN;

    // global-load mapping: 2 threads per row, float4 each
    const int lr = tid >> 1;
    const int lc = (tid & 1) << 2;
    const float* Ap = A + (size_t)(bm + lr) * K + lc;
    const float* Bp = B + (size_t)(bn + lr) * K + lc;

    // compute mapping: 16x16 thread grid
    const int tx = tid & 15;
    const int ty = tid >> 4;
    const int m0 = ty * 8;            // rows m0..m0+7
    const int n0 = tx * 4;            // cols n0..n0+3 and 64+n0..64+n0+3

    float acc[8][8];
#pragma unroll
    for (int i = 0; i < 8; i++)
#pragma unroll
        for (int j = 0; j < 8; j++) acc[i][j] = 0.f;

    // prologue: stage 0
    float4 a4 = *(const float4*)Ap;
    float4 b4 = *(const float4*)Bp;
    As[0][lc + 0][lr] = a4.x; As[0][lc + 1][lr] = a4.y;
    As[0][lc + 2][lr] = a4.z; As[0][lc + 3][lr] = a4.w;
    Bs[0][lc + 0][lr] = b4.x; Bs[0][lc + 1][lr] = b4.y;
    Bs[0][lc + 2][lr] = b4.z; Bs[0][lc + 3][lr] = b4.w;
    __syncthreads();

    int buf = 0;
    for (int k0 = BK; k0 <= K; k0 += BK) {
        const bool more = (k0 < K);
        if (more) {
            a4 = *(const float4*)(Ap + k0);
            b4 = *(const float4*)(Bp + k0);
        }
#pragma unroll
        for (int kk = 0; kk < BK; kk++) {
            float4 af0 = *(const float4*)&As[buf][kk][m0];
            float4 af1 = *(const float4*)&As[buf][kk][m0 + 4];
            float4 bf0 = *(const float4*)&Bs[buf][kk][n0];
            float4 bf1 = *(const float4*)&Bs[buf][kk][n0 + 64];
            float a[8] = {af0.x, af0.y, af0.z, af0.w, af1.x, af1.y, af1.z, af1.w};
            float bb[8] = {bf0.x, bf0.y, bf0.z, bf0.w, bf1.x, bf1.y, bf1.z, bf1.w};
#pragma unroll
            for (int i = 0; i < 8; i++)
#pragma unroll
                for (int j = 0; j < 8; j++)
                    acc[i][j] = fmaf(a[i], bb[j], acc[i][j]);
        }
        if (more) {
            buf ^= 1;
            As[buf][lc + 0][lr] = a4.x; As[buf][lc + 1][lr] = a4.y;
            As[buf][lc + 2][lr] = a4.z; As[buf][lc + 3][lr] = a4.w;
            Bs[buf][lc + 0][lr] = b4.x; Bs[buf][lc + 1][lr] = b4.y;
            Bs[buf][lc + 2][lr] = b4.z; Bs[buf][lc + 3][lr] = b4.w;
        }
        __syncthreads();
    }

    float* Cp = C + (size_t)(bm + m0) * N + bn;
#pragma unroll
    for (int i = 0; i < 8; i++) {
        float4 r0 = make_float4(acc[i][0], acc[i][1], acc[i][2], acc[i][3]);
        float4 r1 = make_float4(acc[i][4], acc[i][5], acc[i][6], acc[i][7]);
        *(float4*)(Cp + (size_t)i * N + n0)      = r0;
        *(float4*)(Cp + (size_t)i * N + n0 + 64) = r1;
    }
}

// ---------------------------------------------------------------------------
// Causal flash attention, fp32. One thread per query row (128 rows per CTA).
// K/V tiles of 32 keys in smem (broadcast reads -> conflict-free).
// ---------------------------------------------------------------------------
#define QB 128
#define KB 32
#define KPAD (DK + 4)

__global__ __launch_bounds__(128)
void attn_kernel(const float* __restrict__ Q, const float* __restrict__ K,
                 const float* __restrict__ V, float* __restrict__ O)
{
    __shared__ float Ks[KB][KPAD];   // padded to kill store-phase conflicts
    __shared__ float Vs[KB][KPAD];

    const int bh = blockIdx.y;               // 0..31
    const int b = bh >> 4, h = bh & 15;
    const int tid = threadIdx.x;
    const int qi = blockIdx.x * QB + tid;    // query index in sequence
    const size_t base = (size_t)b * SEQ * D_MODEL + (size_t)h * DK;

    // load q row, pre-scaled by 1/sqrt(d_k)
    const float scale = 0.125f;
    float q[DK];
    {
        const float* qp = Q + base + (size_t)qi * D_MODEL;
#pragma unroll
        for (int d = 0; d < DK; d += 4) {
            float4 t = *(const float4*)(qp + d);
            q[d] = t.x * scale; q[d + 1] = t.y * scale;
            q[d + 2] = t.z * scale; q[d + 3] = t.w * scale;
        }
    }

    float o[DK];
#pragma unroll
    for (int d = 0; d < DK; d++) o[d] = 0.f;
    float m = NEG_INF, l = 0.f;

    const int nkb = (blockIdx.x + 1) * (QB / KB);
    const int lrr = tid >> 2;           // 0..31 : key row within tile
    const int lcc = (tid & 3) << 4;     // 0,16,32,48

    for (int kb = 0; kb < nkb; kb++) {
        const int k0 = kb * KB;
        __syncthreads();                // protect previous tile reads
        {
            const float* kp = K + base + (size_t)(k0 + lrr) * D_MODEL + lcc;
            const float* vp = V + base + (size_t)(k0 + lrr) * D_MODEL + lcc;
#pragma unroll
            for (int c = 0; c < 16; c += 4) {
                *(float4*)&Ks[lrr][lcc + c] = *(const float4*)(kp + c);
                *(float4*)&Vs[lrr][lcc + c] = *(const float4*)(vp + c);
            }
        }
        __syncthreads();

        float s[KB];
        float bmax = NEG_INF;
#pragma unroll
        for (int j = 0; j < KB; j++) {
            float acc = 0.f;
#pragma unroll
            for (int d = 0; d < DK; d += 4) {
                float4 kv = *(const float4*)&Ks[j][d];
                acc = fmaf(q[d], kv.x, acc);
                acc = fmaf(q[d + 1], kv.y, acc);
                acc = fmaf(q[d + 2], kv.z, acc);
                acc = fmaf(q[d + 3], kv.w, acc);
            }
            if (k0 + j > qi) acc = NEG_INF;   // causal mask
            s[j] = acc;
            bmax = fmaxf(bmax, acc);
        }

        const float mnew = fmaxf(m, bmax);
        if (mnew == NEG_INF) continue;        // this thread fully masked so far

        const float alpha = __expf(m - mnew); // exp(-inf)=0 handles first block
        l *= alpha;
#pragma unroll
        for (int d = 0; d < DK; d++) o[d] *= alpha;

#pragma unroll
        for (int j = 0; j < KB; j++) {
            const float p = __expf(s[j] - mnew);
            l += p;
#pragma unroll
            for (int d = 0; d < DK; d += 4) {
                float4 v = *(const float4*)&Vs[j][d];
                o[d]     = fmaf(p, v.x, o[d]);
                o[d + 1] = fmaf(p, v.y, o[d + 1]);
                o[d + 2] = fmaf(p, v.z, o[d + 2]);
                o[d + 3] = fmaf(p, v.w, o[d + 3]);
            }
        }
        m = mnew;
    }

    const float invl = 1.f / l;               // diagonal key always present
    float* op = O + base + (size_t)qi * D_MODEL;
#pragma unroll
    for (int d = 0; d < DK; d += 4) {
        float4 t = make_float4(o[d] * invl, o[d + 1] * invl,
                               o[d + 2] * invl, o[d + 3] * invl);
        *(float4*)(op + d) = t;
    }
}

// ---------------------------------------------------------------------------
extern "C" void kernel_launch(void* const* d_in, const int* in_sizes, int n_in,
                              void* d_out, int out_size)
{
    (void)in_sizes; (void)n_in; (void)out_size;
    const float* x  = (const float*)d_in[0];
    const float* Wq = (const float*)d_in[1];
    const float* Wk = (const float*)d_in[2];
    const float* Wv = (const float*)d_in[3];
    const float* Wo = (const float*)d_in[4];
    float* out = (float*)d_out;

    float *Qb, *Kb, *Vb, *Ob;
    cudaGetSymbolAddress((void**)&Qb, g_Q);
    cudaGetSymbolAddress((void**)&Kb, g_K);
    cudaGetSymbolAddress((void**)&Vb, g_V);
    cudaGetSymbolAddress((void**)&Ob, g_O);

    dim3 gg(D_MODEL / 128, MTOT / 128);   // (8, 32)
    sgemm_nt<<<gg, 256>>>(x, Wq, Qb, MTOT, D_MODEL, D_MODEL);
    sgemm_nt<<<gg, 256>>>(x, Wk, Kb, MTOT, D_MODEL, D_MODEL);
    sgemm_nt<<<gg, 256>>>(x, Wv, Vb, MTOT, D_MODEL, D_MODEL);

    attn_kernel<<<dim3(SEQ / QB, BATCH * NHEAD), 128>>>(Qb, Kb, Vb, Ob);

    sgemm_nt<<<gg, 256>>>(Ob, Wo, out, MTOT, D_MODEL, D_MODEL);
}

// round 5
// speedup vs baseline: 1.3556x; 1.3556x over previous
#include <cuda_runtime.h>
#include <cuda_bf16.h>
#include <cstdint>

#define D_MODEL 1024
#define NHEAD   16
#define DK      64
#define BATCH   2
#define SEQ     2048
#define MTOT    (BATCH * SEQ)   // 4096

#define NEG_INF __int_as_float(0xff800000)

// ---------------------------------------------------------------------------
// Scratch (__device__ globals: allocations are forbidden)
// ---------------------------------------------------------------------------
__device__ float g_Q[MTOT * D_MODEL];
__device__ float g_K[MTOT * D_MODEL];
__device__ float g_V[MTOT * D_MODEL];
__device__ float g_O[MTOT * D_MODEL];

__device__ __nv_bfloat16 g_x_hi[MTOT * D_MODEL];
__device__ __nv_bfloat16 g_x_lo[MTOT * D_MODEL];
__device__ __nv_bfloat16 g_o_hi[MTOT * D_MODEL];
__device__ __nv_bfloat16 g_o_lo[MTOT * D_MODEL];
__device__ __nv_bfloat16 g_w_hi[4][D_MODEL * D_MODEL];
__device__ __nv_bfloat16 g_w_lo[4][D_MODEL * D_MODEL];

// ---------------------------------------------------------------------------
// Base-ISA helpers (NO tcgen05 — harness ptxas targets plain sm_103)
// ---------------------------------------------------------------------------
__device__ __forceinline__ uint32_t smem_to_u32(const void* p) {
    uint32_t a;
    asm("{ .reg .u64 t; cvta.to.shared.u64 t, %1; cvt.u32.u64 %0, t; }" : "=r"(a) : "l"(p));
    return a;
}
#define SW128(o) ((o) ^ (((o) >> 3) & 0x70))

#define CP_ASYNC16(dst, src) \
    asm volatile("cp.async.cg.shared.global [%0], [%1], 16;" :: "r"(dst), "l"(src))
#define CP_COMMIT() asm volatile("cp.async.commit_group;" ::: "memory")
#define CP_WAIT(n)  asm volatile("cp.async.wait_group %0;" :: "n"(n) : "memory")

#define LDSM_X4(r0, r1, r2, r3, addr) \
    asm volatile("ldmatrix.sync.aligned.m8n8.x4.shared.b16 {%0,%1,%2,%3}, [%4];" \
                 : "=r"(r0), "=r"(r1), "=r"(r2), "=r"(r3) : "r"(addr))

#define MMA_BF16(c, a, b) \
    asm volatile("mma.sync.aligned.m16n8k16.row.col.f32.bf16.bf16.f32 " \
                 "{%0,%1,%2,%3}, {%4,%5,%6,%7}, {%8,%9}, {%0,%1,%2,%3};" \
                 : "+f"((c)[0]), "+f"((c)[1]), "+f"((c)[2]), "+f"((c)[3]) \
                 : "r"((a)[0]), "r"((a)[1]), "r"((a)[2]), "r"((a)[3]), \
                   "r"((b)[0]), "r"((b)[1]))

// ---------------------------------------------------------------------------
// fp32 -> bf16 hi/lo split (2-way decomposition)
// ---------------------------------------------------------------------------
__global__ __launch_bounds__(256)
void cvt_split(const float* __restrict__ in, __nv_bfloat16* __restrict__ hi,
               __nv_bfloat16* __restrict__ lo, int n4)
{
    int i = blockIdx.x * 256 + threadIdx.x;
    if (i >= n4) return;
    float4 v = ((const float4*)in)[i];
    __nv_bfloat16 h0 = __float2bfloat16(v.x);
    __nv_bfloat16 h1 = __float2bfloat16(v.y);
    __nv_bfloat16 h2 = __float2bfloat16(v.z);
    __nv_bfloat16 h3 = __float2bfloat16(v.w);
    __nv_bfloat16 l0 = __float2bfloat16(v.x - __bfloat162float(h0));
    __nv_bfloat16 l1 = __float2bfloat16(v.y - __bfloat162float(h1));
    __nv_bfloat16 l2 = __float2bfloat16(v.z - __bfloat162float(h2));
    __nv_bfloat16 l3 = __float2bfloat16(v.w - __bfloat162float(h3));
    ((__nv_bfloat162*)hi)[2 * i]     = __nv_bfloat162(h0, h1);
    ((__nv_bfloat162*)hi)[2 * i + 1] = __nv_bfloat162(h2, h3);
    ((__nv_bfloat162*)lo)[2 * i]     = __nv_bfloat162(l0, l1);
    ((__nv_bfloat162*)lo)[2 * i + 1] = __nv_bfloat162(l2, l3);
}

// ---------------------------------------------------------------------------
// bf16-split GEMM via mma.sync (HMMA):
//   C[m][n] = sum_k (Ahi+Alo)[m][k]*(Bhi+Blo)[n][k], lo*lo dropped.
// CTA tile 128x128, 8 warps (2x4), warp tile 64x32, K-chunk 64, cp.async
// double buffering, SW128-swizzled smem (conflict-free ldmatrix).
// ---------------------------------------------------------------------------
#define KC        64
#define NCHUNK    (D_MODEL / KC)      // 16
#define TILE_B    16384               // 128 rows x 128 bytes
#define BUF_B     (4 * TILE_B)        // Ahi, Alo, Bhi, Blo
#define GEMM_SMEM (2 * BUF_B)         // 131072

__device__ __forceinline__ void cp_tile(uint32_t dst_base, const __nv_bfloat16* src, int tid)
{
    // 128 rows x 64 bf16 (128B/row); src row stride = D_MODEL elements
#pragma unroll
    for (int u = tid; u < 1024; u += 256) {
        int row = u >> 3, c = u & 7;
        uint32_t off = row * 128 + c * 16;
        CP_ASYNC16(dst_base + SW128(off), src + (size_t)row * D_MODEL + c * 8);
    }
}

__global__ __launch_bounds__(256, 1)
void gemm_mma(const __nv_bfloat16* __restrict__ Ahi, const __nv_bfloat16* __restrict__ Alo,
              const __nv_bfloat16* __restrict__ Bhi, const __nv_bfloat16* __restrict__ Blo,
              float* __restrict__ C)
{
    extern __shared__ char smem[];
    const uint32_t sbase = smem_to_u32(smem);
    const int tid = threadIdx.x;
    const int wid = tid >> 5, lane = tid & 31;
    const int bm = blockIdx.y * 128;
    const int bn = blockIdx.x * 128;
    const int m0 = (wid & 1) * 64;     // warp row offset in tile
    const int n0 = (wid >> 1) * 32;    // warp col offset in tile

    const __nv_bfloat16* pAh = Ahi + (size_t)bm * D_MODEL;
    const __nv_bfloat16* pAl = Alo + (size_t)bm * D_MODEL;
    const __nv_bfloat16* pBh = Bhi + (size_t)bn * D_MODEL;
    const __nv_bfloat16* pBl = Blo + (size_t)bn * D_MODEL;

    float acc[4][4][4];
#pragma unroll
    for (int i = 0; i < 4; i++)
#pragma unroll
        for (int j = 0; j < 4; j++)
#pragma unroll
            for (int r = 0; r < 4; r++) acc[i][j][r] = 0.f;

    // ldmatrix lane-address components
    const int ra = lane & 15;          // A: row within 16-row block
    const int ca = lane >> 4;          // A: k-half selector (0/1)
    const int qb = lane >> 3;          // B: matrix index 0..3
    const int l7 = lane & 7;           // B: row within 8-row block

    // prologue: chunk 0 -> buf 0
    cp_tile(sbase + 0 * TILE_B, pAh, tid);
    cp_tile(sbase + 1 * TILE_B, pAl, tid);
    cp_tile(sbase + 2 * TILE_B, pBh, tid);
    cp_tile(sbase + 3 * TILE_B, pBl, tid);
    CP_COMMIT();

    for (int ch = 0; ch < NCHUNK; ch++) {
        const int buf = ch & 1;
        if (ch + 1 < NCHUNK) {
            const uint32_t nb = sbase + (buf ^ 1) * BUF_B;
            const int kc = (ch + 1) * KC;
            cp_tile(nb + 0 * TILE_B, pAh + kc, tid);
            cp_tile(nb + 1 * TILE_B, pAl + kc, tid);
            cp_tile(nb + 2 * TILE_B, pBh + kc, tid);
            cp_tile(nb + 3 * TILE_B, pBl + kc, tid);
            CP_COMMIT();
            CP_WAIT(1);
        } else {
            CP_WAIT(0);
        }
        __syncthreads();

        const uint32_t aH = sbase + buf * BUF_B + 0 * TILE_B;
        const uint32_t aL = sbase + buf * BUF_B + 1 * TILE_B;
        const uint32_t bH = sbase + buf * BUF_B + 2 * TILE_B;
        const uint32_t bL = sbase + buf * BUF_B + 3 * TILE_B;

#pragma unroll
        for (int ks = 0; ks < 4; ks++) {
            uint32_t ah[16], al[16];
#pragma unroll
            for (int i = 0; i < 4; i++) {
                uint32_t off = (uint32_t)(m0 + i * 16 + ra) * 128 + (ks * 2 + ca) * 16;
                uint32_t sw = SW128(off);
                LDSM_X4(ah[4 * i], ah[4 * i + 1], ah[4 * i + 2], ah[4 * i + 3], aH + sw);
                LDSM_X4(al[4 * i], al[4 * i + 1], al[4 * i + 2], al[4 * i + 3], aL + sw);
            }
            uint32_t bh[8], bl[8];
#pragma unroll
            for (int jj = 0; jj < 2; jj++) {
                uint32_t off = (uint32_t)(n0 + (jj * 2 + (qb >> 1)) * 8 + l7) * 128
                             + (ks * 2 + (qb & 1)) * 16;
                uint32_t sw = SW128(off);
                LDSM_X4(bh[4 * jj], bh[4 * jj + 1], bh[4 * jj + 2], bh[4 * jj + 3], bH + sw);
                LDSM_X4(bl[4 * jj], bl[4 * jj + 1], bl[4 * jj + 2], bl[4 * jj + 3], bL + sw);
            }
#pragma unroll
            for (int i = 0; i < 4; i++)
#pragma unroll
                for (int j = 0; j < 4; j++) {
                    MMA_BF16(acc[i][j], &ah[4 * i], &bh[2 * j]);
                    MMA_BF16(acc[i][j], &ah[4 * i], &bl[2 * j]);
                    MMA_BF16(acc[i][j], &al[4 * i], &bh[2 * j]);
                }
        }
        __syncthreads();
    }

    // epilogue
    const int g = lane >> 2, t = lane & 3;
#pragma unroll
    for (int i = 0; i < 4; i++) {
#pragma unroll
        for (int j = 0; j < 4; j++) {
            float* cp0 = C + (size_t)(bm + m0 + i * 16 + g) * D_MODEL + bn + n0 + j * 8 + 2 * t;
            float* cp1 = cp0 + 8 * D_MODEL;
            *(float2*)cp0 = make_float2(acc[i][j][0], acc[i][j][1]);
            *(float2*)cp1 = make_float2(acc[i][j][2], acc[i][j][3]);
        }
    }
}

// ---------------------------------------------------------------------------
// Causal flash attention, fp32 SIMT (validated in R1)
// ---------------------------------------------------------------------------
#define QB 128
#define KB 32
#define KPAD (DK + 4)

__global__ __launch_bounds__(128)
void attn_kernel(const float* __restrict__ Q, const float* __restrict__ K,
                 const float* __restrict__ V, float* __restrict__ O)
{
    __shared__ float Ks[KB][KPAD];
    __shared__ float Vs[KB][KPAD];

    const int bh = blockIdx.y;
    const int b = bh >> 4, h = bh & 15;
    const int tid = threadIdx.x;
    const int qi = blockIdx.x * QB + tid;
    const size_t base = (size_t)b * SEQ * D_MODEL + (size_t)h * DK;

    const float scale = 0.125f;
    float q[DK];
    {
        const float* qp = Q + base + (size_t)qi * D_MODEL;
#pragma unroll
        for (int d = 0; d < DK; d += 4) {
            float4 t = *(const float4*)(qp + d);
            q[d] = t.x * scale; q[d + 1] = t.y * scale;
            q[d + 2] = t.z * scale; q[d + 3] = t.w * scale;
        }
    }

    float o[DK];
#pragma unroll
    for (int d = 0; d < DK; d++) o[d] = 0.f;
    float m = NEG_INF, l = 0.f;

    const int nkb = (blockIdx.x + 1) * (QB / KB);
    const int lrr = tid >> 2;
    const int lcc = (tid & 3) << 4;

    for (int kb = 0; kb < nkb; kb++) {
        const int k0 = kb * KB;
        __syncthreads();
        {
            const float* kp = K + base + (size_t)(k0 + lrr) * D_MODEL + lcc;
            const float* vp = V + base + (size_t)(k0 + lrr) * D_MODEL + lcc;
#pragma unroll
            for (int c = 0; c < 16; c += 4) {
                *(float4*)&Ks[lrr][lcc + c] = *(const float4*)(kp + c);
                *(float4*)&Vs[lrr][lcc + c] = *(const float4*)(vp + c);
            }
        }
        __syncthreads();

        float s[KB];
        float bmax = NEG_INF;
#pragma unroll
        for (int j = 0; j < KB; j++) {
            float acc = 0.f;
#pragma unroll
            for (int d = 0; d < DK; d += 4) {
                float4 kv = *(const float4*)&Ks[j][d];
                acc = fmaf(q[d], kv.x, acc);
                acc = fmaf(q[d + 1], kv.y, acc);
                acc = fmaf(q[d + 2], kv.z, acc);
                acc = fmaf(q[d + 3], kv.w, acc);
            }
            if (k0 + j > qi) acc = NEG_INF;
            s[j] = acc;
            bmax = fmaxf(bmax, acc);
        }

        const float mnew = fmaxf(m, bmax);
        if (mnew == NEG_INF) continue;

        const float alpha = __expf(m - mnew);
        l *= alpha;
#pragma unroll
        for (int d = 0; d < DK; d++) o[d] *= alpha;

#pragma unroll
        for (int j = 0; j < KB; j++) {
            const float p = __expf(s[j] - mnew);
            l += p;
#pragma unroll
            for (int d = 0; d < DK; d += 4) {
                float4 v = *(const float4*)&Vs[j][d];
                o[d]     = fmaf(p, v.x, o[d]);
                o[d + 1] = fmaf(p, v.y, o[d + 1]);
                o[d + 2] = fmaf(p, v.z, o[d + 2]);
                o[d + 3] = fmaf(p, v.w, o[d + 3]);
            }
        }
        m = mnew;
    }

    const float invl = 1.f / l;
    float* op = O + base + (size_t)qi * D_MODEL;
#pragma unroll
    for (int d = 0; d < DK; d += 4) {
        float4 t = make_float4(o[d] * invl, o[d + 1] * invl,
                               o[d + 2] * invl, o[d + 3] * invl);
        *(float4*)(op + d) = t;
    }
}

// ---------------------------------------------------------------------------
extern "C" void kernel_launch(void* const* d_in, const int* in_sizes, int n_in,
                              void* d_out, int out_size)
{
    (void)in_sizes; (void)n_in; (void)out_size;
    const float* x  = (const float*)d_in[0];
    const float* Wq = (const float*)d_in[1];
    const float* Wk = (const float*)d_in[2];
    const float* Wv = (const float*)d_in[3];
    const float* Wo = (const float*)d_in[4];
    float* out = (float*)d_out;

    float *Qb, *Kb, *Vb, *Ob;
    cudaGetSymbolAddress((void**)&Qb, g_Q);
    cudaGetSymbolAddress((void**)&Kb, g_K);
    cudaGetSymbolAddress((void**)&Vb, g_V);
    cudaGetSymbolAddress((void**)&Ob, g_O);
    __nv_bfloat16 *xhi, *xlo, *ohi, *olo, *whi, *wlo;
    cudaGetSymbolAddress((void**)&xhi, g_x_hi);
    cudaGetSymbolAddress((void**)&xlo, g_x_lo);
    cudaGetSymbolAddress((void**)&ohi, g_o_hi);
    cudaGetSymbolAddress((void**)&olo, g_o_lo);
    cudaGetSymbolAddress((void**)&whi, g_w_hi);
    cudaGetSymbolAddress((void**)&wlo, g_w_lo);

    cudaFuncSetAttribute(gemm_mma, cudaFuncAttributeMaxDynamicSharedMemorySize, GEMM_SMEM);

    const int NX4 = MTOT * D_MODEL / 4;      // 1048576
    const int NW4 = D_MODEL * D_MODEL / 4;   // 262144
    const int WSZ = D_MODEL * D_MODEL;

    cvt_split<<<NX4 / 256, 256>>>(x, xhi, xlo, NX4);
    cvt_split<<<NW4 / 256, 256>>>(Wq, whi + 0 * WSZ, wlo + 0 * WSZ, NW4);
    cvt_split<<<NW4 / 256, 256>>>(Wk, whi + 1 * WSZ, wlo + 1 * WSZ, NW4);
    cvt_split<<<NW4 / 256, 256>>>(Wv, whi + 2 * WSZ, wlo + 2 * WSZ, NW4);
    cvt_split<<<NW4 / 256, 256>>>(Wo, whi + 3 * WSZ, wlo + 3 * WSZ, NW4);

    dim3 gg(D_MODEL / 128, MTOT / 128);   // (8, 32)
    gemm_mma<<<gg, 256, GEMM_SMEM>>>(xhi, xlo, whi + 0 * WSZ, wlo + 0 * WSZ, Qb);
    gemm_mma<<<gg, 256, GEMM_SMEM>>>(xhi, xlo, whi + 1 * WSZ, wlo + 1 * WSZ, Kb);
    gemm_mma<<<gg, 256, GEMM_SMEM>>>(xhi, xlo, whi + 2 * WSZ, wlo + 2 * WSZ, Vb);

    attn_kernel<<<dim3(SEQ / QB, BATCH * NHEAD), 128>>>(Qb, Kb, Vb, Ob);

    cvt_split<<<NX4 / 256, 256>>>(Ob, ohi, olo, NX4);
    gemm_mma<<<gg, 256, GEMM_SMEM>>>(ohi, olo, whi + 3 * WSZ, wlo + 3 * WSZ, out);
}

// round 6
// speedup vs baseline: 3.8130x; 2.8128x over previous
#include <cuda_runtime.h>
#include <cuda_bf16.h>
#include <cstdint>

#define D_MODEL 1024
#define NHEAD   16
#define DK      64
#define BATCH   2
#define SEQ     2048
#define MTOT    (BATCH * SEQ)   // 4096
#define BH      (BATCH * NHEAD) // 32

#define NEG_INF __int_as_float(0xff800000)

// ---------------------------------------------------------------------------
// Scratch (__device__ globals: allocations are forbidden)
// ---------------------------------------------------------------------------
__device__ float g_Q[MTOT * D_MODEL];
__device__ float g_K[MTOT * D_MODEL];
__device__ float g_V[MTOT * D_MODEL];

__device__ __nv_bfloat16 g_x_hi[MTOT * D_MODEL];
__device__ __nv_bfloat16 g_x_lo[MTOT * D_MODEL];
__device__ __nv_bfloat16 g_o_hi[MTOT * D_MODEL];
__device__ __nv_bfloat16 g_o_lo[MTOT * D_MODEL];
__device__ __nv_bfloat16 g_w_hi[4][D_MODEL * D_MODEL];
__device__ __nv_bfloat16 g_w_lo[4][D_MODEL * D_MODEL];

// head-major bf16 hi/lo for attention
__device__ __nv_bfloat16 g_qh[BH * SEQ * DK];
__device__ __nv_bfloat16 g_ql[BH * SEQ * DK];
__device__ __nv_bfloat16 g_kh[BH * SEQ * DK];
__device__ __nv_bfloat16 g_kl[BH * SEQ * DK];
__device__ __nv_bfloat16 g_vth[BH * DK * SEQ];  // transposed: [bh][d][s]
__device__ __nv_bfloat16 g_vtl[BH * DK * SEQ];

// ---------------------------------------------------------------------------
// Base-ISA helpers (NO tcgen05 — harness ptxas targets plain sm_103)
// ---------------------------------------------------------------------------
__device__ __forceinline__ uint32_t smem_to_u32(const void* p) {
    uint32_t a;
    asm("{ .reg .u64 t; cvta.to.shared.u64 t, %1; cvt.u32.u64 %0, t; }" : "=r"(a) : "l"(p));
    return a;
}
#define SW128(o) ((o) ^ (((o) >> 3) & 0x70))

#define CP_ASYNC16(dst, src) \
    asm volatile("cp.async.cg.shared.global [%0], [%1], 16;" :: "r"(dst), "l"(src))
#define CP_COMMIT() asm volatile("cp.async.commit_group;" ::: "memory")
#define CP_WAIT(n)  asm volatile("cp.async.wait_group %0;" :: "n"(n) : "memory")

#define LDSM_X4(r0, r1, r2, r3, addr) \
    asm volatile("ldmatrix.sync.aligned.m8n8.x4.shared.b16 {%0,%1,%2,%3}, [%4];" \
                 : "=r"(r0), "=r"(r1), "=r"(r2), "=r"(r3) : "r"(addr))

#define MMA_BF16(c, a, b) \
    asm volatile("mma.sync.aligned.m16n8k16.row.col.f32.bf16.bf16.f32 " \
                 "{%0,%1,%2,%3}, {%4,%5,%6,%7}, {%8,%9}, {%0,%1,%2,%3};" \
                 : "+f"((c)[0]), "+f"((c)[1]), "+f"((c)[2]), "+f"((c)[3]) \
                 : "r"((a)[0]), "r"((a)[1]), "r"((a)[2]), "r"((a)[3]), \
                   "r"((b)[0]), "r"((b)[1]))

__device__ __forceinline__ void split2(float x, float y, uint32_t& hi, uint32_t& lo) {
    __nv_bfloat16 hx = __float2bfloat16(x), hy = __float2bfloat16(y);
    __nv_bfloat16 lx = __float2bfloat16(x - __bfloat162float(hx));
    __nv_bfloat16 ly = __float2bfloat16(y - __bfloat162float(hy));
    __nv_bfloat162 th(hx, hy), tl(lx, ly);
    hi = *(uint32_t*)&th;
    lo = *(uint32_t*)&tl;
}

// ---------------------------------------------------------------------------
// fp32 -> bf16 hi/lo split (flat layout)
// ---------------------------------------------------------------------------
__global__ __launch_bounds__(256)
void cvt_split(const float* __restrict__ in, __nv_bfloat16* __restrict__ hi,
               __nv_bfloat16* __restrict__ lo, int n4)
{
    int i = blockIdx.x * 256 + threadIdx.x;
    if (i >= n4) return;
    float4 v = ((const float4*)in)[i];
    uint32_t h0, l0, h1, l1;
    split2(v.x, v.y, h0, l0);
    split2(v.z, v.w, h1, l1);
    ((uint32_t*)hi)[2 * i] = h0;     ((uint32_t*)hi)[2 * i + 1] = h1;
    ((uint32_t*)lo)[2 * i] = l0;     ((uint32_t*)lo)[2 * i + 1] = l1;
}

// ---------------------------------------------------------------------------
// fp32 [m,1024] -> bf16 hi/lo head-major [bh][s][64], with scale
// ---------------------------------------------------------------------------
__global__ __launch_bounds__(256)
void cvt_head(const float* __restrict__ src, __nv_bfloat16* __restrict__ hi,
              __nv_bfloat16* __restrict__ lo, float scale)
{
    int i = blockIdx.x * 256 + threadIdx.x;     // 1,048,576 threads, 4 elems each
    int d4 = i & 15;
    int s  = (i >> 4) & (SEQ - 1);
    int bh = i >> 15;
    int b = bh >> 4, h = bh & 15;
    float4 v = *(const float4*)(src + ((size_t)(b * SEQ + s)) * D_MODEL + h * DK + d4 * 4);
    uint32_t h0, l0, h1, l1;
    split2(v.x * scale, v.y * scale, h0, l0);
    split2(v.z * scale, v.w * scale, h1, l1);
    size_t dst = ((size_t)bh * SEQ + s) * DK + d4 * 4;
    *(uint32_t*)(hi + dst) = h0; *(uint32_t*)(hi + dst + 2) = h1;
    *(uint32_t*)(lo + dst) = l0; *(uint32_t*)(lo + dst + 2) = l1;
}

// ---------------------------------------------------------------------------
// fp32 V [m,1024] -> bf16 hi/lo TRANSPOSED per head [bh][d][s]
// ---------------------------------------------------------------------------
__global__ __launch_bounds__(256)
void cvt_vt(const float* __restrict__ src, __nv_bfloat16* __restrict__ hi,
            __nv_bfloat16* __restrict__ lo)
{
    __shared__ float ts[64][65];
    const int bh = blockIdx.y, s0 = blockIdx.x * 64;
    const int b = bh >> 4, h = bh & 15;
    const int tx = threadIdx.x & 63, ty = threadIdx.x >> 6;   // (64, 4)

#pragma unroll
    for (int it = 0; it < 16; it++) {
        int sl = it * 4 + ty;
        ts[sl][tx] = src[((size_t)(b * SEQ + s0 + sl)) * D_MODEL + h * DK + tx];
    }
    __syncthreads();
#pragma unroll
    for (int it = 0; it < 16; it++) {
        int d = it * 4 + ty;
        float v = ts[tx][d];
        __nv_bfloat16 hv = __float2bfloat16(v);
        __nv_bfloat16 lv = __float2bfloat16(v - __bfloat162float(hv));
        size_t dst = ((size_t)bh * DK + d) * SEQ + s0 + tx;
        hi[dst] = hv;
        lo[dst] = lv;
    }
}

// ---------------------------------------------------------------------------
// bf16-split GEMM via mma.sync (validated R5)
// ---------------------------------------------------------------------------
#define KC        64
#define NCHUNK    (D_MODEL / KC)      // 16
#define TILE_B    16384
#define BUF_B     (4 * TILE_B)
#define GEMM_SMEM (2 * BUF_B)         // 131072

__device__ __forceinline__ void cp_tile(uint32_t dst_base, const __nv_bfloat16* src, int tid)
{
#pragma unroll
    for (int u = tid; u < 1024; u += 256) {
        int row = u >> 3, c = u & 7;
        uint32_t off = row * 128 + c * 16;
        CP_ASYNC16(dst_base + SW128(off), src + (size_t)row * D_MODEL + c * 8);
    }
}

__global__ __launch_bounds__(256, 1)
void gemm_mma(const __nv_bfloat16* __restrict__ Ahi, const __nv_bfloat16* __restrict__ Alo,
              const __nv_bfloat16* __restrict__ Bhi, const __nv_bfloat16* __restrict__ Blo,
              float* __restrict__ C)
{
    extern __shared__ char smem[];
    const uint32_t sbase = smem_to_u32(smem);
    const int tid = threadIdx.x;
    const int wid = tid >> 5, lane = tid & 31;
    const int bm = blockIdx.y * 128;
    const int bn = blockIdx.x * 128;
    const int m0 = (wid & 1) * 64;
    const int n0 = (wid >> 1) * 32;

    const __nv_bfloat16* pAh = Ahi + (size_t)bm * D_MODEL;
    const __nv_bfloat16* pAl = Alo + (size_t)bm * D_MODEL;
    const __nv_bfloat16* pBh = Bhi + (size_t)bn * D_MODEL;
    const __nv_bfloat16* pBl = Blo + (size_t)bn * D_MODEL;

    float acc[4][4][4];
#pragma unroll
    for (int i = 0; i < 4; i++)
#pragma unroll
        for (int j = 0; j < 4; j++)
#pragma unroll
            for (int r = 0; r < 4; r++) acc[i][j][r] = 0.f;

    const int ra = lane & 15;
    const int ca = lane >> 4;
    const int qb = lane >> 3;
    const int l7 = lane & 7;

    cp_tile(sbase + 0 * TILE_B, pAh, tid);
    cp_tile(sbase + 1 * TILE_B, pAl, tid);
    cp_tile(sbase + 2 * TILE_B, pBh, tid);
    cp_tile(sbase + 3 * TILE_B, pBl, tid);
    CP_COMMIT();

    for (int ch = 0; ch < NCHUNK; ch++) {
        const int buf = ch & 1;
        if (ch + 1 < NCHUNK) {
            const uint32_t nb = sbase + (buf ^ 1) * BUF_B;
            const int kc = (ch + 1) * KC;
            cp_tile(nb + 0 * TILE_B, pAh + kc, tid);
            cp_tile(nb + 1 * TILE_B, pAl + kc, tid);
            cp_tile(nb + 2 * TILE_B, pBh + kc, tid);
            cp_tile(nb + 3 * TILE_B, pBl + kc, tid);
            CP_COMMIT();
            CP_WAIT(1);
        } else {
            CP_WAIT(0);
        }
        __syncthreads();

        const uint32_t aH = sbase + buf * BUF_B + 0 * TILE_B;
        const uint32_t aL = sbase + buf * BUF_B + 1 * TILE_B;
        const uint32_t bH = sbase + buf * BUF_B + 2 * TILE_B;
        const uint32_t bL = sbase + buf * BUF_B + 3 * TILE_B;

#pragma unroll
        for (int ks = 0; ks < 4; ks++) {
            uint32_t ah[16], al[16];
#pragma unroll
            for (int i = 0; i < 4; i++) {
                uint32_t off = (uint32_t)(m0 + i * 16 + ra) * 128 + (ks * 2 + ca) * 16;
                uint32_t sw = SW128(off);
                LDSM_X4(ah[4 * i], ah[4 * i + 1], ah[4 * i + 2], ah[4 * i + 3], aH + sw);
                LDSM_X4(al[4 * i], al[4 * i + 1], al[4 * i + 2], al[4 * i + 3], aL + sw);
            }
            uint32_t bh[8], bl[8];
#pragma unroll
            for (int jj = 0; jj < 2; jj++) {
                uint32_t off = (uint32_t)(n0 + (jj * 2 + (qb >> 1)) * 8 + l7) * 128
                             + (ks * 2 + (qb & 1)) * 16;
                uint32_t sw = SW128(off);
                LDSM_X4(bh[4 * jj], bh[4 * jj + 1], bh[4 * jj + 2], bh[4 * jj + 3], bH + sw);
                LDSM_X4(bl[4 * jj], bl[4 * jj + 1], bl[4 * jj + 2], bl[4 * jj + 3], bL + sw);
            }
#pragma unroll
            for (int i = 0; i < 4; i++)
#pragma unroll
                for (int j = 0; j < 4; j++) {
                    MMA_BF16(acc[i][j], &ah[4 * i], &bh[2 * j]);
                    MMA_BF16(acc[i][j], &ah[4 * i], &bl[2 * j]);
                    MMA_BF16(acc[i][j], &al[4 * i], &bh[2 * j]);
                }
        }
        __syncthreads();
    }

    const int g = lane >> 2, t = lane & 3;
#pragma unroll
    for (int i = 0; i < 4; i++) {
#pragma unroll
        for (int j = 0; j < 4; j++) {
            float* cp0 = C + (size_t)(bm + m0 + i * 16 + g) * D_MODEL + bn + n0 + j * 8 + 2 * t;
            float* cp1 = cp0 + 8 * D_MODEL;
            *(float2*)cp0 = make_float2(acc[i][j][0], acc[i][j][1]);
            *(float2*)cp1 = make_float2(acc[i][j][2], acc[i][j][3]);
        }
    }
}

// ---------------------------------------------------------------------------
// Tensor-core causal flash attention (mma.sync, bf16 hi/lo split).
// CTA: 128 q-rows x 1 head; 8 warps x 16 q-rows. Key blocks of 64.
// Writes output directly as hi/lo split in [m, 1024] layout.
// ---------------------------------------------------------------------------
#define ATT_SMEM (32768 + 2 * 32768)   // Q(hi+lo) + 2 x (Kh,Kl,Vh,Vl)

__global__ __launch_bounds__(256, 1)
void attn_mma(const __nv_bfloat16* __restrict__ Qh, const __nv_bfloat16* __restrict__ Ql,
              const __nv_bfloat16* __restrict__ Kh, const __nv_bfloat16* __restrict__ Kl,
              const __nv_bfloat16* __restrict__ Vh, const __nv_bfloat16* __restrict__ Vl,
              __nv_bfloat16* __restrict__ Ohi, __nv_bfloat16* __restrict__ Olo)
{
    extern __shared__ char smem[];
    const uint32_t sb = smem_to_u32(smem);
    const int tid = threadIdx.x, wid = tid >> 5, lane = tid & 31;
    const int qblk = gridDim.x - 1 - blockIdx.x;   // heavy CTAs first
    const int bh = blockIdx.y;
    const int b = bh >> 4, h = bh & 15;
    const int qr0 = qblk * 128 + wid * 16;
    const int g = lane >> 2, t = lane & 3;
    const int qb2 = lane >> 3, l7 = lane & 7;
    const int ra = lane & 15, ca = lane >> 4;

    const uint32_t QH = sb, QL = sb + 16384;
    const uint32_t BUF0 = sb + 32768;

    // --- Q tile load (128 x 64 bf16, hi+lo) ---
    {
        const __nv_bfloat16* qh_g = Qh + ((size_t)bh * SEQ + qblk * 128) * DK;
        const __nv_bfloat16* ql_g = Ql + ((size_t)bh * SEQ + qblk * 128) * DK;
#pragma unroll
        for (int u = tid; u < 1024; u += 256) {
            int row = u >> 3, c = u & 7;
            uint32_t sw = SW128((uint32_t)(row * 128 + c * 16));
            CP_ASYNC16(QH + sw, qh_g + (size_t)row * DK + c * 8);
            CP_ASYNC16(QL + sw, ql_g + (size_t)row * DK + c * 8);
        }
        CP_COMMIT();
    }

    const int nkb = 2 * (qblk + 1);

    // kv tile loader: K[k0+r][d] rows and Vt[d][k0+c] rows, 64x128B each
    auto load_kv = [&](uint32_t dbuf, int k0) {
#pragma unroll
        for (int u = tid; u < 512; u += 256) {
            int r = u >> 3, c = u & 7;
            uint32_t sw = SW128((uint32_t)(r * 128 + c * 16));
            const size_t kg = ((size_t)bh * SEQ + k0 + r) * DK + c * 8;
            CP_ASYNC16(dbuf + sw,         Kh + kg);
            CP_ASYNC16(dbuf + 8192 + sw,  Kl + kg);
            const size_t vg = ((size_t)bh * DK + r) * SEQ + k0 + c * 8;
            CP_ASYNC16(dbuf + 16384 + sw, Vh + vg);
            CP_ASYNC16(dbuf + 24576 + sw, Vl + vg);
        }
    };

    load_kv(BUF0, 0);
    CP_COMMIT();

    // wait for Q (leave kv0 possibly in flight)
    CP_WAIT(1);
    __syncthreads();

    // --- Q fragments (persistent) ---
    uint32_t qhf[16], qlf[16];
#pragma unroll
    for (int ks = 0; ks < 4; ks++) {
        uint32_t sw = SW128((uint32_t)((wid * 16 + ra) * 128 + (ks * 2 + ca) * 16));
        LDSM_X4(qhf[4 * ks], qhf[4 * ks + 1], qhf[4 * ks + 2], qhf[4 * ks + 3], QH + sw);
        LDSM_X4(qlf[4 * ks], qlf[4 * ks + 1], qlf[4 * ks + 2], qlf[4 * ks + 3], QL + sw);
    }

    float o[8][4];
#pragma unroll
    for (int j = 0; j < 8; j++)
#pragma unroll
        for (int r = 0; r < 4; r++) o[j][r] = 0.f;
    float m0 = NEG_INF, m1 = NEG_INF, l0 = 0.f, l1 = 0.f;

    for (int kb = 0; kb < nkb; kb++) {
        const int k0 = kb * 64;
        const int buf = kb & 1;
        if (kb + 1 < nkb) {
            load_kv(BUF0 + (buf ^ 1) * 32768, (kb + 1) * 64);
            CP_COMMIT();
            CP_WAIT(1);
        } else {
            CP_WAIT(0);
        }
        __syncthreads();

        if (k0 <= qr0 + 15) {   // else: fully masked for this warp
            const uint32_t KHs = BUF0 + buf * 32768;
            const uint32_t KLs = KHs + 8192;
            const uint32_t VHs = KHs + 16384;
            const uint32_t VLs = KHs + 24576;

            // --- S = Q K^T ---
            float sf[8][4];
#pragma unroll
            for (int j = 0; j < 8; j++)
#pragma unroll
                for (int r = 0; r < 4; r++) sf[j][r] = 0.f;

#pragma unroll
            for (int ks = 0; ks < 4; ks++) {
                uint32_t bhf[16], blf[16];
#pragma unroll
                for (int jj = 0; jj < 4; jj++) {
                    uint32_t sw = SW128((uint32_t)(((jj * 2 + (qb2 >> 1)) * 8 + l7) * 128
                                                   + (ks * 2 + (qb2 & 1)) * 16));
                    LDSM_X4(bhf[4 * jj], bhf[4 * jj + 1], bhf[4 * jj + 2], bhf[4 * jj + 3], KHs + sw);
                    LDSM_X4(blf[4 * jj], blf[4 * jj + 1], blf[4 * jj + 2], blf[4 * jj + 3], KLs + sw);
                }
#pragma unroll
                for (int j = 0; j < 8; j++) {
                    MMA_BF16(sf[j], &qhf[4 * ks], &bhf[2 * j]);
                    MMA_BF16(sf[j], &qhf[4 * ks], &blf[2 * j]);
                    MMA_BF16(sf[j], &qlf[4 * ks], &bhf[2 * j]);
                }
            }

            // --- causal mask ---
            if (k0 + 63 > qr0) {
                const int row0 = qr0 + g, row1 = row0 + 8;
#pragma unroll
                for (int j = 0; j < 8; j++) {
                    const int key = k0 + 8 * j + 2 * t;
                    if (key     > row0) sf[j][0] = NEG_INF;
                    if (key + 1 > row0) sf[j][1] = NEG_INF;
                    if (key     > row1) sf[j][2] = NEG_INF;
                    if (key + 1 > row1) sf[j][3] = NEG_INF;
                }
            }

            // --- online softmax ---
            float mx0 = NEG_INF, mx1 = NEG_INF;
#pragma unroll
            for (int j = 0; j < 8; j++) {
                mx0 = fmaxf(mx0, fmaxf(sf[j][0], sf[j][1]));
                mx1 = fmaxf(mx1, fmaxf(sf[j][2], sf[j][3]));
            }
            mx0 = fmaxf(mx0, __shfl_xor_sync(0xffffffffu, mx0, 1));
            mx0 = fmaxf(mx0, __shfl_xor_sync(0xffffffffu, mx0, 2));
            mx1 = fmaxf(mx1, __shfl_xor_sync(0xffffffffu, mx1, 1));
            mx1 = fmaxf(mx1, __shfl_xor_sync(0xffffffffu, mx1, 2));
            const float mn0 = fmaxf(m0, mx0), mn1 = fmaxf(m1, mx1);
            const float a0 = __expf(m0 - mn0), a1 = __expf(m1 - mn1);
            m0 = mn0; m1 = mn1;

            float rs0 = 0.f, rs1 = 0.f;
            uint32_t ph[16], pl[16];
#pragma unroll
            for (int j = 0; j < 8; j++) {
                float p0 = __expf(sf[j][0] - mn0);
                float p1 = __expf(sf[j][1] - mn0);
                float p2 = __expf(sf[j][2] - mn1);
                float p3 = __expf(sf[j][3] - mn1);
                rs0 += p0 + p1;
                rs1 += p2 + p3;
                const int ks2 = j >> 1, hf = j & 1;
                split2(p0, p1, ph[4 * ks2 + 2 * hf],     pl[4 * ks2 + 2 * hf]);
                split2(p2, p3, ph[4 * ks2 + 2 * hf + 1], pl[4 * ks2 + 2 * hf + 1]);
            }
            rs0 += __shfl_xor_sync(0xffffffffu, rs0, 1);
            rs0 += __shfl_xor_sync(0xffffffffu, rs0, 2);
            rs1 += __shfl_xor_sync(0xffffffffu, rs1, 1);
            rs1 += __shfl_xor_sync(0xffffffffu, rs1, 2);
            l0 = l0 * a0 + rs0;
            l1 = l1 * a1 + rs1;

#pragma unroll
            for (int j = 0; j < 8; j++) {
                o[j][0] *= a0; o[j][1] *= a0;
                o[j][2] *= a1; o[j][3] *= a1;
            }

            // --- O += P V (B from transposed V tile) ---
#pragma unroll
            for (int ks = 0; ks < 4; ks++) {
                uint32_t vhf[16], vlf[16];
#pragma unroll
                for (int jj = 0; jj < 4; jj++) {
                    uint32_t sw = SW128((uint32_t)(((jj * 2 + (qb2 >> 1)) * 8 + l7) * 128
                                                   + (ks * 2 + (qb2 & 1)) * 16));
                    LDSM_X4(vhf[4 * jj], vhf[4 * jj + 1], vhf[4 * jj + 2], vhf[4 * jj + 3], VHs + sw);
                    LDSM_X4(vlf[4 * jj], vlf[4 * jj + 1], vlf[4 * jj + 2], vlf[4 * jj + 3], VLs + sw);
                }
#pragma unroll
                for (int j = 0; j < 8; j++) {
                    MMA_BF16(o[j], &ph[4 * ks], &vhf[2 * j]);
                    MMA_BF16(o[j], &ph[4 * ks], &vlf[2 * j]);
                    MMA_BF16(o[j], &pl[4 * ks], &vhf[2 * j]);
                }
            }
        }
        __syncthreads();
    }

    // --- write O as hi/lo split directly in [m, 1024] layout ---
    const float il0 = 1.f / l0, il1 = 1.f / l1;
    const size_t r0 = (size_t)(b * SEQ + qr0 + g) * D_MODEL + h * DK;
    const size_t r1 = r0 + (size_t)8 * D_MODEL;
#pragma unroll
    for (int j = 0; j < 8; j++) {
        const int c = 8 * j + 2 * t;
        uint32_t hv, lv;
        split2(o[j][0] * il0, o[j][1] * il0, hv, lv);
        *(uint32_t*)(Ohi + r0 + c) = hv;
        *(uint32_t*)(Olo + r0 + c) = lv;
        split2(o[j][2] * il1, o[j][3] * il1, hv, lv);
        *(uint32_t*)(Ohi + r1 + c) = hv;
        *(uint32_t*)(Olo + r1 + c) = lv;
    }
}

// ---------------------------------------------------------------------------
extern "C" void kernel_launch(void* const* d_in, const int* in_sizes, int n_in,
                              void* d_out, int out_size)
{
    (void)in_sizes; (void)n_in; (void)out_size;
    const float* x  = (const float*)d_in[0];
    const float* Wq = (const float*)d_in[1];
    const float* Wk = (const float*)d_in[2];
    const float* Wv = (const float*)d_in[3];
    const float* Wo = (const float*)d_in[4];
    float* out = (float*)d_out;

    float *Qb, *Kb, *Vb;
    cudaGetSymbolAddress((void**)&Qb, g_Q);
    cudaGetSymbolAddress((void**)&Kb, g_K);
    cudaGetSymbolAddress((void**)&Vb, g_V);
    __nv_bfloat16 *xhi, *xlo, *ohi, *olo, *whi, *wlo;
    cudaGetSymbolAddress((void**)&xhi, g_x_hi);
    cudaGetSymbolAddress((void**)&xlo, g_x_lo);
    cudaGetSymbolAddress((void**)&ohi, g_o_hi);
    cudaGetSymbolAddress((void**)&olo, g_o_lo);
    cudaGetSymbolAddress((void**)&whi, g_w_hi);
    cudaGetSymbolAddress((void**)&wlo, g_w_lo);
    __nv_bfloat16 *qh, *ql, *kh, *kl, *vth, *vtl;
    cudaGetSymbolAddress((void**)&qh,  g_qh);
    cudaGetSymbolAddress((void**)&ql,  g_ql);
    cudaGetSymbolAddress((void**)&kh,  g_kh);
    cudaGetSymbolAddress((void**)&kl,  g_kl);
    cudaGetSymbolAddress((void**)&vth, g_vth);
    cudaGetSymbolAddress((void**)&vtl, g_vtl);

    cudaFuncSetAttribute(gemm_mma, cudaFuncAttributeMaxDynamicSharedMemorySize, GEMM_SMEM);
    cudaFuncSetAttribute(attn_mma, cudaFuncAttributeMaxDynamicSharedMemorySize, ATT_SMEM);

    const int NX4 = MTOT * D_MODEL / 4;
    const int NW4 = D_MODEL * D_MODEL / 4;
    const int WSZ = D_MODEL * D_MODEL;

    cvt_split<<<NX4 / 256, 256>>>(x, xhi, xlo, NX4);
    cvt_split<<<NW4 / 256, 256>>>(Wq, whi + 0 * WSZ, wlo + 0 * WSZ, NW4);
    cvt_split<<<NW4 / 256, 256>>>(Wk, whi + 1 * WSZ, wlo + 1 * WSZ, NW4);
    cvt_split<<<NW4 / 256, 256>>>(Wv, whi + 2 * WSZ, wlo + 2 * WSZ, NW4);
    cvt_split<<<NW4 / 256, 256>>>(Wo, whi + 3 * WSZ, wlo + 3 * WSZ, NW4);

    dim3 gg(D_MODEL / 128, MTOT / 128);   // (8, 32)
    gemm_mma<<<gg, 256, GEMM_SMEM>>>(xhi, xlo, whi + 0 * WSZ, wlo + 0 * WSZ, Qb);
    gemm_mma<<<gg, 256, GEMM_SMEM>>>(xhi, xlo, whi + 1 * WSZ, wlo + 1 * WSZ, Kb);
    gemm_mma<<<gg, 256, GEMM_SMEM>>>(xhi, xlo, whi + 2 * WSZ, wlo + 2 * WSZ, Vb);

    const int NH = BH * SEQ * DK / 4 / 256;   // blocks for cvt_head
    cvt_head<<<NH, 256>>>(Qb, qh, ql, 0.125f);
    cvt_head<<<NH, 256>>>(Kb, kh, kl, 1.0f);
    cvt_vt<<<dim3(SEQ / 64, BH), 256>>>(Vb, vth, vtl);

    attn_mma<<<dim3(SEQ / 128, BH), 256, ATT_SMEM>>>(qh, ql, kh, kl, vth, vtl, ohi, olo);

    gemm_mma<<<gg, 256, GEMM_SMEM>>>(ohi, olo, whi + 3 * WSZ, wlo + 3 * WSZ, out);
}

// round 7
// speedup vs baseline: 3.8140x; 1.0003x over previous
#include <cuda_runtime.h>
#include <cuda_bf16.h>
#include <cstdint>

#define D_MODEL 1024
#define NHEAD   16
#define DK      64
#define BATCH   2
#define SEQ     2048
#define MTOT    (BATCH * SEQ)   // 4096
#define BH      (BATCH * NHEAD) // 32

#define NEG_INF __int_as_float(0xff800000)

// ---------------------------------------------------------------------------
// Scratch (__device__ globals: allocations are forbidden)
// ---------------------------------------------------------------------------
__device__ float g_Q[MTOT * D_MODEL];
__device__ float g_K[MTOT * D_MODEL];
__device__ float g_V[MTOT * D_MODEL];

__device__ __nv_bfloat16 g_x_hi[MTOT * D_MODEL];
__device__ __nv_bfloat16 g_x_lo[MTOT * D_MODEL];
__device__ __nv_bfloat16 g_o_hi[MTOT * D_MODEL];
__device__ __nv_bfloat16 g_o_lo[MTOT * D_MODEL];
__device__ __nv_bfloat16 g_w_hi[4][D_MODEL * D_MODEL];
__device__ __nv_bfloat16 g_w_lo[4][D_MODEL * D_MODEL];

// head-major bf16 hi/lo for attention
__device__ __nv_bfloat16 g_qh[BH * SEQ * DK];
__device__ __nv_bfloat16 g_ql[BH * SEQ * DK];
__device__ __nv_bfloat16 g_kh[BH * SEQ * DK];
__device__ __nv_bfloat16 g_kl[BH * SEQ * DK];
__device__ __nv_bfloat16 g_vth[BH * DK * SEQ];  // transposed: [bh][d][s]
__device__ __nv_bfloat16 g_vtl[BH * DK * SEQ];

// ---------------------------------------------------------------------------
// Base-ISA helpers (NO tcgen05 — harness ptxas targets plain sm_103)
// ---------------------------------------------------------------------------
__device__ __forceinline__ uint32_t smem_to_u32(const void* p) {
    uint32_t a;
    asm("{ .reg .u64 t; cvta.to.shared.u64 t, %1; cvt.u32.u64 %0, t; }" : "=r"(a) : "l"(p));
    return a;
}
#define SW128(o) ((o) ^ (((o) >> 3) & 0x70))

#define CP_ASYNC16(dst, src) \
    asm volatile("cp.async.cg.shared.global [%0], [%1], 16;" :: "r"(dst), "l"(src))
#define CP_COMMIT() asm volatile("cp.async.commit_group;" ::: "memory")
#define CP_WAIT(n)  asm volatile("cp.async.wait_group %0;" :: "n"(n) : "memory")

#define LDSM_X4(r0, r1, r2, r3, addr) \
    asm volatile("ldmatrix.sync.aligned.m8n8.x4.shared.b16 {%0,%1,%2,%3}, [%4];" \
                 : "=r"(r0), "=r"(r1), "=r"(r2), "=r"(r3) : "r"(addr))

#define MMA_BF16(c, a, b) \
    asm volatile("mma.sync.aligned.m16n8k16.row.col.f32.bf16.bf16.f32 " \
                 "{%0,%1,%2,%3}, {%4,%5,%6,%7}, {%8,%9}, {%0,%1,%2,%3};" \
                 : "+f"((c)[0]), "+f"((c)[1]), "+f"((c)[2]), "+f"((c)[3]) \
                 : "r"((a)[0]), "r"((a)[1]), "r"((a)[2]), "r"((a)[3]), \
                   "r"((b)[0]), "r"((b)[1]))

__device__ __forceinline__ void split2(float x, float y, uint32_t& hi, uint32_t& lo) {
    __nv_bfloat16 hx = __float2bfloat16(x), hy = __float2bfloat16(y);
    __nv_bfloat16 lx = __float2bfloat16(x - __bfloat162float(hx));
    __nv_bfloat16 ly = __float2bfloat16(y - __bfloat162float(hy));
    __nv_bfloat162 th(hx, hy), tl(lx, ly);
    hi = *(uint32_t*)&th;
    lo = *(uint32_t*)&tl;
}

// ---------------------------------------------------------------------------
// fp32 -> bf16 hi/lo split (flat layout)
// ---------------------------------------------------------------------------
__global__ __launch_bounds__(256)
void cvt_split(const float* __restrict__ in, __nv_bfloat16* __restrict__ hi,
               __nv_bfloat16* __restrict__ lo, int n4)
{
    int i = blockIdx.x * 256 + threadIdx.x;
    if (i >= n4) return;
    float4 v = ((const float4*)in)[i];
    uint32_t h0, l0, h1, l1;
    split2(v.x, v.y, h0, l0);
    split2(v.z, v.w, h1, l1);
    ((uint32_t*)hi)[2 * i] = h0;     ((uint32_t*)hi)[2 * i + 1] = h1;
    ((uint32_t*)lo)[2 * i] = l0;     ((uint32_t*)lo)[2 * i + 1] = l1;
}

// ---------------------------------------------------------------------------
// fp32 [m,1024] -> bf16 hi/lo head-major [bh][s][64], with scale
// ---------------------------------------------------------------------------
__global__ __launch_bounds__(256)
void cvt_head(const float* __restrict__ src, __nv_bfloat16* __restrict__ hi,
              __nv_bfloat16* __restrict__ lo, float scale)
{
    int i = blockIdx.x * 256 + threadIdx.x;     // 1,048,576 threads, 4 elems each
    int d4 = i & 15;
    int s  = (i >> 4) & (SEQ - 1);
    int bh = i >> 15;
    int b = bh >> 4, h = bh & 15;
    float4 v = *(const float4*)(src + ((size_t)(b * SEQ + s)) * D_MODEL + h * DK + d4 * 4);
    uint32_t h0, l0, h1, l1;
    split2(v.x * scale, v.y * scale, h0, l0);
    split2(v.z * scale, v.w * scale, h1, l1);
    size_t dst = ((size_t)bh * SEQ + s) * DK + d4 * 4;
    *(uint32_t*)(hi + dst) = h0; *(uint32_t*)(hi + dst + 2) = h1;
    *(uint32_t*)(lo + dst) = l0; *(uint32_t*)(lo + dst + 2) = l1;
}

// ---------------------------------------------------------------------------
// fp32 V [m,1024] -> bf16 hi/lo TRANSPOSED per head [bh][d][s]
// ---------------------------------------------------------------------------
__global__ __launch_bounds__(256)
void cvt_vt(const float* __restrict__ src, __nv_bfloat16* __restrict__ hi,
            __nv_bfloat16* __restrict__ lo)
{
    __shared__ float ts[64][65];
    const int bh = blockIdx.y, s0 = blockIdx.x * 64;
    const int b = bh >> 4, h = bh & 15;
    const int tx = threadIdx.x & 63, ty = threadIdx.x >> 6;   // (64, 4)

#pragma unroll
    for (int it = 0; it < 16; it++) {
        int sl = it * 4 + ty;
        ts[sl][tx] = src[((size_t)(b * SEQ + s0 + sl)) * D_MODEL + h * DK + tx];
    }
    __syncthreads();
#pragma unroll
    for (int it = 0; it < 16; it++) {
        int d = it * 4 + ty;
        float v = ts[tx][d];
        __nv_bfloat16 hv = __float2bfloat16(v);
        __nv_bfloat16 lv = __float2bfloat16(v - __bfloat162float(hv));
        size_t dst = ((size_t)bh * DK + d) * SEQ + s0 + tx;
        hi[dst] = hv;
        lo[dst] = lv;
    }
}

// ---------------------------------------------------------------------------
// bf16-split GEMM via mma.sync (validated R5)
// ---------------------------------------------------------------------------
#define KC        64
#define NCHUNK    (D_MODEL / KC)      // 16
#define TILE_B    16384
#define BUF_B     (4 * TILE_B)
#define GEMM_SMEM (2 * BUF_B)         // 131072

__device__ __forceinline__ void cp_tile(uint32_t dst_base, const __nv_bfloat16* src, int tid)
{
#pragma unroll
    for (int u = tid; u < 1024; u += 256) {
        int row = u >> 3, c = u & 7;
        uint32_t off = row * 128 + c * 16;
        CP_ASYNC16(dst_base + SW128(off), src + (size_t)row * D_MODEL + c * 8);
    }
}

__global__ __launch_bounds__(256, 1)
void gemm_mma(const __nv_bfloat16* __restrict__ Ahi, const __nv_bfloat16* __restrict__ Alo,
              const __nv_bfloat16* __restrict__ Bhi, const __nv_bfloat16* __restrict__ Blo,
              float* __restrict__ C)
{
    extern __shared__ char smem[];
    const uint32_t sbase = smem_to_u32(smem);
    const int tid = threadIdx.x;
    const int wid = tid >> 5, lane = tid & 31;
    const int bm = blockIdx.y * 128;
    const int bn = blockIdx.x * 128;
    const int m0 = (wid & 1) * 64;
    const int n0 = (wid >> 1) * 32;

    const __nv_bfloat16* pAh = Ahi + (size_t)bm * D_MODEL;
    const __nv_bfloat16* pAl = Alo + (size_t)bm * D_MODEL;
    const __nv_bfloat16* pBh = Bhi + (size_t)bn * D_MODEL;
    const __nv_bfloat16* pBl = Blo + (size_t)bn * D_MODEL;

    float acc[4][4][4];
#pragma unroll
    for (int i = 0; i < 4; i++)
#pragma unroll
        for (int j = 0; j < 4; j++)
#pragma unroll
            for (int r = 0; r < 4; r++) acc[i][j][r] = 0.f;

    const int ra = lane & 15;
    const int ca = lane >> 4;
    const int qb = lane >> 3;
    const int l7 = lane & 7;

    cp_tile(sbase + 0 * TILE_B, pAh, tid);
    cp_tile(sbase + 1 * TILE_B, pAl, tid);
    cp_tile(sbase + 2 * TILE_B, pBh, tid);
    cp_tile(sbase + 3 * TILE_B, pBl, tid);
    CP_COMMIT();

    for (int ch = 0; ch < NCHUNK; ch++) {
        const int buf = ch & 1;
        if (ch + 1 < NCHUNK) {
            const uint32_t nb = sbase + (buf ^ 1) * BUF_B;
            const int kc = (ch + 1) * KC;
            cp_tile(nb + 0 * TILE_B, pAh + kc, tid);
            cp_tile(nb + 1 * TILE_B, pAl + kc, tid);
            cp_tile(nb + 2 * TILE_B, pBh + kc, tid);
            cp_tile(nb + 3 * TILE_B, pBl + kc, tid);
            CP_COMMIT();
            CP_WAIT(1);
        } else {
            CP_WAIT(0);
        }
        __syncthreads();

        const uint32_t aH = sbase + buf * BUF_B + 0 * TILE_B;
        const uint32_t aL = sbase + buf * BUF_B + 1 * TILE_B;
        const uint32_t bH = sbase + buf * BUF_B + 2 * TILE_B;
        const uint32_t bL = sbase + buf * BUF_B + 3 * TILE_B;

#pragma unroll
        for (int ks = 0; ks < 4; ks++) {
            uint32_t ah[16], al[16];
#pragma unroll
            for (int i = 0; i < 4; i++) {
                uint32_t off = (uint32_t)(m0 + i * 16 + ra) * 128 + (ks * 2 + ca) * 16;
                uint32_t sw = SW128(off);
                LDSM_X4(ah[4 * i], ah[4 * i + 1], ah[4 * i + 2], ah[4 * i + 3], aH + sw);
                LDSM_X4(al[4 * i], al[4 * i + 1], al[4 * i + 2], al[4 * i + 3], aL + sw);
            }
            uint32_t bh[8], bl[8];
#pragma unroll
            for (int jj = 0; jj < 2; jj++) {
                uint32_t off = (uint32_t)(n0 + (jj * 2 + (qb >> 1)) * 8 + l7) * 128
                             + (ks * 2 + (qb & 1)) * 16;
                uint32_t sw = SW128(off);
                LDSM_X4(bh[4 * jj], bh[4 * jj + 1], bh[4 * jj + 2], bh[4 * jj + 3], bH + sw);
                LDSM_X4(bl[4 * jj], bl[4 * jj + 1], bl[4 * jj + 2], bl[4 * jj + 3], bL + sw);
            }
#pragma unroll
            for (int i = 0; i < 4; i++)
#pragma unroll
                for (int j = 0; j < 4; j++) {
                    MMA_BF16(acc[i][j], &ah[4 * i], &bh[2 * j]);
                    MMA_BF16(acc[i][j], &ah[4 * i], &bl[2 * j]);
                    MMA_BF16(acc[i][j], &al[4 * i], &bh[2 * j]);
                }
        }
        __syncthreads();
    }

    const int g = lane >> 2, t = lane & 3;
#pragma unroll
    for (int i = 0; i < 4; i++) {
#pragma unroll
        for (int j = 0; j < 4; j++) {
            float* cp0 = C + (size_t)(bm + m0 + i * 16 + g) * D_MODEL + bn + n0 + j * 8 + 2 * t;
            float* cp1 = cp0 + 8 * D_MODEL;
            *(float2*)cp0 = make_float2(acc[i][j][0], acc[i][j][1]);
            *(float2*)cp1 = make_float2(acc[i][j][2], acc[i][j][3]);
        }
    }
}

// ---------------------------------------------------------------------------
// Tensor-core causal flash attention (mma.sync, bf16 hi/lo split).
// CTA: 128 q-rows x 1 head; 8 warps x 16 q-rows. Key blocks of 64.
// Writes output directly as hi/lo split in [m, 1024] layout.
// ---------------------------------------------------------------------------
#define ATT_SMEM (32768 + 2 * 32768)   // Q(hi+lo) + 2 x (Kh,Kl,Vh,Vl)

__global__ __launch_bounds__(256, 1)
void attn_mma(const __nv_bfloat16* __restrict__ Qh, const __nv_bfloat16* __restrict__ Ql,
              const __nv_bfloat16* __restrict__ Kh, const __nv_bfloat16* __restrict__ Kl,
              const __nv_bfloat16* __restrict__ Vh, const __nv_bfloat16* __restrict__ Vl,
              __nv_bfloat16* __restrict__ Ohi, __nv_bfloat16* __restrict__ Olo)
{
    extern __shared__ char smem[];
    const uint32_t sb = smem_to_u32(smem);
    const int tid = threadIdx.x, wid = tid >> 5, lane = tid & 31;
    const int qblk = gridDim.x - 1 - blockIdx.x;   // heavy CTAs first
    const int bh = blockIdx.y;
    const int b = bh >> 4, h = bh & 15;
    const int qr0 = qblk * 128 + wid * 16;
    const int g = lane >> 2, t = lane & 3;
    const int qb2 = lane >> 3, l7 = lane & 7;
    const int ra = lane & 15, ca = lane >> 4;

    const uint32_t QH = sb, QL = sb + 16384;
    const uint32_t BUF0 = sb + 32768;

    // --- Q tile load (128 x 64 bf16, hi+lo) ---
    {
        const __nv_bfloat16* qh_g = Qh + ((size_t)bh * SEQ + qblk * 128) * DK;
        const __nv_bfloat16* ql_g = Ql + ((size_t)bh * SEQ + qblk * 128) * DK;
#pragma unroll
        for (int u = tid; u < 1024; u += 256) {
            int row = u >> 3, c = u & 7;
            uint32_t sw = SW128((uint32_t)(row * 128 + c * 16));
            CP_ASYNC16(QH + sw, qh_g + (size_t)row * DK + c * 8);
            CP_ASYNC16(QL + sw, ql_g + (size_t)row * DK + c * 8);
        }
        CP_COMMIT();
    }

    const int nkb = 2 * (qblk + 1);

    // kv tile loader: K[k0+r][d] rows and Vt[d][k0+c] rows, 64x128B each
    auto load_kv = [&](uint32_t dbuf, int k0) {
#pragma unroll
        for (int u = tid; u < 512; u += 256) {
            int r = u >> 3, c = u & 7;
            uint32_t sw = SW128((uint32_t)(r * 128 + c * 16));
            const size_t kg = ((size_t)bh * SEQ + k0 + r) * DK + c * 8;
            CP_ASYNC16(dbuf + sw,         Kh + kg);
            CP_ASYNC16(dbuf + 8192 + sw,  Kl + kg);
            const size_t vg = ((size_t)bh * DK + r) * SEQ + k0 + c * 8;
            CP_ASYNC16(dbuf + 16384 + sw, Vh + vg);
            CP_ASYNC16(dbuf + 24576 + sw, Vl + vg);
        }
    };

    load_kv(BUF0, 0);
    CP_COMMIT();

    // wait for Q (leave kv0 possibly in flight)
    CP_WAIT(1);
    __syncthreads();

    // --- Q fragments (persistent) ---
    uint32_t qhf[16], qlf[16];
#pragma unroll
    for (int ks = 0; ks < 4; ks++) {
        uint32_t sw = SW128((uint32_t)((wid * 16 + ra) * 128 + (ks * 2 + ca) * 16));
        LDSM_X4(qhf[4 * ks], qhf[4 * ks + 1], qhf[4 * ks + 2], qhf[4 * ks + 3], QH + sw);
        LDSM_X4(qlf[4 * ks], qlf[4 * ks + 1], qlf[4 * ks + 2], qlf[4 * ks + 3], QL + sw);
    }

    float o[8][4];
#pragma unroll
    for (int j = 0; j < 8; j++)
#pragma unroll
        for (int r = 0; r < 4; r++) o[j][r] = 0.f;
    float m0 = NEG_INF, m1 = NEG_INF, l0 = 0.f, l1 = 0.f;

    for (int kb = 0; kb < nkb; kb++) {
        const int k0 = kb * 64;
        const int buf = kb & 1;
        if (kb + 1 < nkb) {
            load_kv(BUF0 + (buf ^ 1) * 32768, (kb + 1) * 64);
            CP_COMMIT();
            CP_WAIT(1);
        } else {
            CP_WAIT(0);
        }
        __syncthreads();

        if (k0 <= qr0 + 15) {   // else: fully masked for this warp
            const uint32_t KHs = BUF0 + buf * 32768;
            const uint32_t KLs = KHs + 8192;
            const uint32_t VHs = KHs + 16384;
            const uint32_t VLs = KHs + 24576;

            // --- S = Q K^T ---
            float sf[8][4];
#pragma unroll
            for (int j = 0; j < 8; j++)
#pragma unroll
                for (int r = 0; r < 4; r++) sf[j][r] = 0.f;

#pragma unroll
            for (int ks = 0; ks < 4; ks++) {
                uint32_t bhf[16], blf[16];
#pragma unroll
                for (int jj = 0; jj < 4; jj++) {
                    uint32_t sw = SW128((uint32_t)(((jj * 2 + (qb2 >> 1)) * 8 + l7) * 128
                                                   + (ks * 2 + (qb2 & 1)) * 16));
                    LDSM_X4(bhf[4 * jj], bhf[4 * jj + 1], bhf[4 * jj + 2], bhf[4 * jj + 3], KHs + sw);
                    LDSM_X4(blf[4 * jj], blf[4 * jj + 1], blf[4 * jj + 2], blf[4 * jj + 3], KLs + sw);
                }
#pragma unroll
                for (int j = 0; j < 8; j++) {
                    MMA_BF16(sf[j], &qhf[4 * ks], &bhf[2 * j]);
                    MMA_BF16(sf[j], &qhf[4 * ks], &blf[2 * j]);
                    MMA_BF16(sf[j], &qlf[4 * ks], &bhf[2 * j]);
                }
            }

            // --- causal mask ---
            if (k0 + 63 > qr0) {
                const int row0 = qr0 + g, row1 = row0 + 8;
#pragma unroll
                for (int j = 0; j < 8; j++) {
                    const int key = k0 + 8 * j + 2 * t;
                    if (key     > row0) sf[j][0] = NEG_INF;
                    if (key + 1 > row0) sf[j][1] = NEG_INF;
                    if (key     > row1) sf[j][2] = NEG_INF;
                    if (key + 1 > row1) sf[j][3] = NEG_INF;
                }
            }

            // --- online softmax ---
            float mx0 = NEG_INF, mx1 = NEG_INF;
#pragma unroll
            for (int j = 0; j < 8; j++) {
                mx0 = fmaxf(mx0, fmaxf(sf[j][0], sf[j][1]));
                mx1 = fmaxf(mx1, fmaxf(sf[j][2], sf[j][3]));
            }
            mx0 = fmaxf(mx0, __shfl_xor_sync(0xffffffffu, mx0, 1));
            mx0 = fmaxf(mx0, __shfl_xor_sync(0xffffffffu, mx0, 2));
            mx1 = fmaxf(mx1, __shfl_xor_sync(0xffffffffu, mx1, 1));
            mx1 = fmaxf(mx1, __shfl_xor_sync(0xffffffffu, mx1, 2));
            const float mn0 = fmaxf(m0, mx0), mn1 = fmaxf(m1, mx1);
            const float a0 = __expf(m0 - mn0), a1 = __expf(m1 - mn1);
            m0 = mn0; m1 = mn1;

            float rs0 = 0.f, rs1 = 0.f;
            uint32_t ph[16], pl[16];
#pragma unroll
            for (int j = 0; j < 8; j++) {
                float p0 = __expf(sf[j][0] - mn0);
                float p1 = __expf(sf[j][1] - mn0);
                float p2 = __expf(sf[j][2] - mn1);
                float p3 = __expf(sf[j][3] - mn1);
                rs0 += p0 + p1;
                rs1 += p2 + p3;
                const int ks2 = j >> 1, hf = j & 1;
                split2(p0, p1, ph[4 * ks2 + 2 * hf],     pl[4 * ks2 + 2 * hf]);
                split2(p2, p3, ph[4 * ks2 + 2 * hf + 1], pl[4 * ks2 + 2 * hf + 1]);
            }
            rs0 += __shfl_xor_sync(0xffffffffu, rs0, 1);
            rs0 += __shfl_xor_sync(0xffffffffu, rs0, 2);
            rs1 += __shfl_xor_sync(0xffffffffu, rs1, 1);
            rs1 += __shfl_xor_sync(0xffffffffu, rs1, 2);
            l0 = l0 * a0 + rs0;
            l1 = l1 * a1 + rs1;

#pragma unroll
            for (int j = 0; j < 8; j++) {
                o[j][0] *= a0; o[j][1] *= a0;
                o[j][2] *= a1; o[j][3] *= a1;
            }

            // --- O += P V (B from transposed V tile) ---
#pragma unroll
            for (int ks = 0; ks < 4; ks++) {
                uint32_t vhf[16], vlf[16];
#pragma unroll
                for (int jj = 0; jj < 4; jj++) {
                    uint32_t sw = SW128((uint32_t)(((jj * 2 + (qb2 >> 1)) * 8 + l7) * 128
                                                   + (ks * 2 + (qb2 & 1)) * 16));
                    LDSM_X4(vhf[4 * jj], vhf[4 * jj + 1], vhf[4 * jj + 2], vhf[4 * jj + 3], VHs + sw);
                    LDSM_X4(vlf[4 * jj], vlf[4 * jj + 1], vlf[4 * jj + 2], vlf[4 * jj + 3], VLs + sw);
                }
#pragma unroll
                for (int j = 0; j < 8; j++) {
                    MMA_BF16(o[j], &ph[4 * ks], &vhf[2 * j]);
                    MMA_BF16(o[j], &ph[4 * ks], &vlf[2 * j]);
                    MMA_BF16(o[j], &pl[4 * ks], &vhf[2 * j]);
                }
            }
        }
        __syncthreads();
    }

    // --- write O as hi/lo split directly in [m, 1024] layout ---
    const float il0 = 1.f / l0, il1 = 1.f / l1;
    const size_t r0 = (size_t)(b * SEQ + qr0 + g) * D_MODEL + h * DK;
    const size_t r1 = r0 + (size_t)8 * D_MODEL;
#pragma unroll
    for (int j = 0; j < 8; j++) {
        const int c = 8 * j + 2 * t;
        uint32_t hv, lv;
        split2(o[j][0] * il0, o[j][1] * il0, hv, lv);
        *(uint32_t*)(Ohi + r0 + c) = hv;
        *(uint32_t*)(Olo + r0 + c) = lv;
        split2(o[j][2] * il1, o[j][3] * il1, hv, lv);
        *(uint32_t*)(Ohi + r1 + c) = hv;
        *(uint32_t*)(Olo + r1 + c) = lv;
    }
}

// ---------------------------------------------------------------------------
extern "C" void kernel_launch(void* const* d_in, const int* in_sizes, int n_in,
                              void* d_out, int out_size)
{
    (void)in_sizes; (void)n_in; (void)out_size;
    const float* x  = (const float*)d_in[0];
    const float* Wq = (const float*)d_in[1];
    const float* Wk = (const float*)d_in[2];
    const float* Wv = (const float*)d_in[3];
    const float* Wo = (const float*)d_in[4];
    float* out = (float*)d_out;

    float *Qb, *Kb, *Vb;
    cudaGetSymbolAddress((void**)&Qb, g_Q);
    cudaGetSymbolAddress((void**)&Kb, g_K);
    cudaGetSymbolAddress((void**)&Vb, g_V);
    __nv_bfloat16 *xhi, *xlo, *ohi, *olo, *whi, *wlo;
    cudaGetSymbolAddress((void**)&xhi, g_x_hi);
    cudaGetSymbolAddress((void**)&xlo, g_x_lo);
    cudaGetSymbolAddress((void**)&ohi, g_o_hi);
    cudaGetSymbolAddress((void**)&olo, g_o_lo);
    cudaGetSymbolAddress((void**)&whi, g_w_hi);
    cudaGetSymbolAddress((void**)&wlo, g_w_lo);
    __nv_bfloat16 *qh, *ql, *kh, *kl, *vth, *vtl;
    cudaGetSymbolAddress((void**)&qh,  g_qh);
    cudaGetSymbolAddress((void**)&ql,  g_ql);
    cudaGetSymbolAddress((void**)&kh,  g_kh);
    cudaGetSymbolAddress((void**)&kl,  g_kl);
    cudaGetSymbolAddress((void**)&vth, g_vth);
    cudaGetSymbolAddress((void**)&vtl, g_vtl);

    cudaFuncSetAttribute(gemm_mma, cudaFuncAttributeMaxDynamicSharedMemorySize, GEMM_SMEM);
    cudaFuncSetAttribute(attn_mma, cudaFuncAttributeMaxDynamicSharedMemorySize, ATT_SMEM);

    const int NX4 = MTOT * D_MODEL / 4;
    const int NW4 = D_MODEL * D_MODEL / 4;
    const int WSZ = D_MODEL * D_MODEL;

    cvt_split<<<NX4 / 256, 256>>>(x, xhi, xlo, NX4);
    cvt_split<<<NW4 / 256, 256>>>(Wq, whi + 0 * WSZ, wlo + 0 * WSZ, NW4);
    cvt_split<<<NW4 / 256, 256>>>(Wk, whi + 1 * WSZ, wlo + 1 * WSZ, NW4);
    cvt_split<<<NW4 / 256, 256>>>(Wv, whi + 2 * WSZ, wlo + 2 * WSZ, NW4);
    cvt_split<<<NW4 / 256, 256>>>(Wo, whi + 3 * WSZ, wlo + 3 * WSZ, NW4);

    dim3 gg(D_MODEL / 128, MTOT / 128);   // (8, 32)
    gemm_mma<<<gg, 256, GEMM_SMEM>>>(xhi, xlo, whi + 0 * WSZ, wlo + 0 * WSZ, Qb);
    gemm_mma<<<gg, 256, GEMM_SMEM>>>(xhi, xlo, whi + 1 * WSZ, wlo + 1 * WSZ, Kb);
    gemm_mma<<<gg, 256, GEMM_SMEM>>>(xhi, xlo, whi + 2 * WSZ, wlo + 2 * WSZ, Vb);

    const int NH = BH * SEQ * DK / 4 / 256;   // blocks for cvt_head
    cvt_head<<<NH, 256>>>(Qb, qh, ql, 0.125f);
    cvt_head<<<NH, 256>>>(Kb, kh, kl, 1.0f);
    cvt_vt<<<dim3(SEQ / 64, BH), 256>>>(Vb, vth, vtl);

    attn_mma<<<dim3(SEQ / 128, BH), 256, ATT_SMEM>>>(qh, ql, kh, kl, vth, vtl, ohi, olo);

    gemm_mma<<<gg, 256, GEMM_SMEM>>>(ohi, olo, whi + 3 * WSZ, wlo + 3 * WSZ, out);
}

// round 8
// speedup vs baseline: 3.8996x; 1.0224x over previous
#include <cuda_runtime.h>
#include <cuda_bf16.h>
#include <cstdint>

#define D_MODEL 1024
#define NHEAD   16
#define DK      64
#define BATCH   2
#define SEQ     2048
#define MTOT    (BATCH * SEQ)   // 4096
#define BH      (BATCH * NHEAD) // 32

#define NEG_INF __int_as_float(0xff800000)

// ---------------------------------------------------------------------------
// Scratch (__device__ globals: allocations are forbidden)
// ---------------------------------------------------------------------------
__device__ __nv_bfloat16 g_x_hi[MTOT * D_MODEL];
__device__ __nv_bfloat16 g_x_lo[MTOT * D_MODEL];
__device__ __nv_bfloat16 g_o_hi[MTOT * D_MODEL];
__device__ __nv_bfloat16 g_o_lo[MTOT * D_MODEL];
__device__ __nv_bfloat16 g_w_hi[4][D_MODEL * D_MODEL];
__device__ __nv_bfloat16 g_w_lo[4][D_MODEL * D_MODEL];

// head-major bf16 hi/lo for attention
__device__ __nv_bfloat16 g_qh[BH * SEQ * DK];
__device__ __nv_bfloat16 g_ql[BH * SEQ * DK];
__device__ __nv_bfloat16 g_kh[BH * SEQ * DK];
__device__ __nv_bfloat16 g_kl[BH * SEQ * DK];
__device__ __nv_bfloat16 g_vth[BH * DK * SEQ];  // transposed: [bh][d][s]
__device__ __nv_bfloat16 g_vtl[BH * DK * SEQ];

// ---------------------------------------------------------------------------
// Base-ISA helpers (NO tcgen05 — harness ptxas targets plain sm_103)
// ---------------------------------------------------------------------------
__device__ __forceinline__ uint32_t smem_to_u32(const void* p) {
    uint32_t a;
    asm("{ .reg .u64 t; cvta.to.shared.u64 t, %1; cvt.u32.u64 %0, t; }" : "=r"(a) : "l"(p));
    return a;
}
#define SW128(o) ((o) ^ (((o) >> 3) & 0x70))

#define CP_ASYNC16(dst, src) \
    asm volatile("cp.async.cg.shared.global [%0], [%1], 16;" :: "r"(dst), "l"(src))
#define CP_COMMIT() asm volatile("cp.async.commit_group;" ::: "memory")
#define CP_WAIT(n)  asm volatile("cp.async.wait_group %0;" :: "n"(n) : "memory")

#define LDSM_X4(r0, r1, r2, r3, addr) \
    asm volatile("ldmatrix.sync.aligned.m8n8.x4.shared.b16 {%0,%1,%2,%3}, [%4];" \
                 : "=r"(r0), "=r"(r1), "=r"(r2), "=r"(r3) : "r"(addr))

#define MMA_BF16(c, a, b) \
    asm volatile("mma.sync.aligned.m16n8k16.row.col.f32.bf16.bf16.f32 " \
                 "{%0,%1,%2,%3}, {%4,%5,%6,%7}, {%8,%9}, {%0,%1,%2,%3};" \
                 : "+f"((c)[0]), "+f"((c)[1]), "+f"((c)[2]), "+f"((c)[3]) \
                 : "r"((a)[0]), "r"((a)[1]), "r"((a)[2]), "r"((a)[3]), \
                   "r"((b)[0]), "r"((b)[1]))

__device__ __forceinline__ void split2(float x, float y, uint32_t& hi, uint32_t& lo) {
    __nv_bfloat16 hx = __float2bfloat16(x), hy = __float2bfloat16(y);
    __nv_bfloat16 lx = __float2bfloat16(x - __bfloat162float(hx));
    __nv_bfloat16 ly = __float2bfloat16(y - __bfloat162float(hy));
    __nv_bfloat162 th(hx, hy), tl(lx, ly);
    hi = *(uint32_t*)&th;
    lo = *(uint32_t*)&tl;
}

// ---------------------------------------------------------------------------
// fp32 -> bf16 hi/lo split (flat layout) — for x
// ---------------------------------------------------------------------------
__global__ __launch_bounds__(256)
void cvt_split(const float* __restrict__ in, __nv_bfloat16* __restrict__ hi,
               __nv_bfloat16* __restrict__ lo, int n4)
{
    int i = blockIdx.x * 256 + threadIdx.x;
    if (i >= n4) return;
    float4 v = ((const float4*)in)[i];
    uint32_t h0, l0, h1, l1;
    split2(v.x, v.y, h0, l0);
    split2(v.z, v.w, h1, l1);
    ((uint32_t*)hi)[2 * i] = h0;     ((uint32_t*)hi)[2 * i + 1] = h1;
    ((uint32_t*)lo)[2 * i] = l0;     ((uint32_t*)lo)[2 * i + 1] = l1;
}

// all 4 weights in one launch (grid.y selects source)
__global__ __launch_bounds__(256)
void cvt_w4(const float* __restrict__ w0, const float* __restrict__ w1,
            const float* __restrict__ w2, const float* __restrict__ w3,
            __nv_bfloat16* __restrict__ hi, __nv_bfloat16* __restrict__ lo, int n4)
{
    const int y = blockIdx.y;
    const float* src = (y == 0) ? w0 : (y == 1) ? w1 : (y == 2) ? w2 : w3;
    hi += (size_t)y * D_MODEL * D_MODEL;
    lo += (size_t)y * D_MODEL * D_MODEL;
    int i = blockIdx.x * 256 + threadIdx.x;
    if (i >= n4) return;
    float4 v = ((const float4*)src)[i];
    uint32_t h0, l0, h1, l1;
    split2(v.x, v.y, h0, l0);
    split2(v.z, v.w, h1, l1);
    ((uint32_t*)hi)[2 * i] = h0;     ((uint32_t*)hi)[2 * i + 1] = h1;
    ((uint32_t*)lo)[2 * i] = l0;     ((uint32_t*)lo)[2 * i + 1] = l1;
}

// ---------------------------------------------------------------------------
// GEMM core (validated R5): 128x128 CTA tile, 8 warps 64x32, KC=64, 3-pass split
// ---------------------------------------------------------------------------
#define KC        64
#define NCHUNK    (D_MODEL / KC)      // 16
#define TILE_B    16384
#define BUF_B     (4 * TILE_B)
#define GEMM_SMEM (2 * BUF_B)         // 131072

__device__ __forceinline__ void cp_tile(uint32_t dst_base, const __nv_bfloat16* src, int tid)
{
#pragma unroll
    for (int u = tid; u < 1024; u += 256) {
        int row = u >> 3, c = u & 7;
        uint32_t off = row * 128 + c * 16;
        CP_ASYNC16(dst_base + SW128(off), src + (size_t)row * D_MODEL + c * 8);
    }
}

// mainloop shared by both GEMM kernels; leaves result in acc
__device__ __forceinline__ void gemm_mainloop(
    uint32_t sbase, int tid, int wid, int lane, int m0, int n0,
    const __nv_bfloat16* pAh, const __nv_bfloat16* pAl,
    const __nv_bfloat16* pBh, const __nv_bfloat16* pBl,
    float acc[4][4][4])
{
#pragma unroll
    for (int i = 0; i < 4; i++)
#pragma unroll
        for (int j = 0; j < 4; j++)
#pragma unroll
            for (int r = 0; r < 4; r++) acc[i][j][r] = 0.f;

    const int ra = lane & 15;
    const int ca = lane >> 4;
    const int qb = lane >> 3;
    const int l7 = lane & 7;

    cp_tile(sbase + 0 * TILE_B, pAh, tid);
    cp_tile(sbase + 1 * TILE_B, pAl, tid);
    cp_tile(sbase + 2 * TILE_B, pBh, tid);
    cp_tile(sbase + 3 * TILE_B, pBl, tid);
    CP_COMMIT();

    for (int ch = 0; ch < NCHUNK; ch++) {
        const int buf = ch & 1;
        if (ch + 1 < NCHUNK) {
            const uint32_t nb = sbase + (buf ^ 1) * BUF_B;
            const int kc = (ch + 1) * KC;
            cp_tile(nb + 0 * TILE_B, pAh + kc, tid);
            cp_tile(nb + 1 * TILE_B, pAl + kc, tid);
            cp_tile(nb + 2 * TILE_B, pBh + kc, tid);
            cp_tile(nb + 3 * TILE_B, pBl + kc, tid);
            CP_COMMIT();
            CP_WAIT(1);
        } else {
            CP_WAIT(0);
        }
        __syncthreads();

        const uint32_t aH = sbase + buf * BUF_B + 0 * TILE_B;
        const uint32_t aL = sbase + buf * BUF_B + 1 * TILE_B;
        const uint32_t bH = sbase + buf * BUF_B + 2 * TILE_B;
        const uint32_t bL = sbase + buf * BUF_B + 3 * TILE_B;

#pragma unroll
        for (int ks = 0; ks < 4; ks++) {
            uint32_t ah[16], al[16];
#pragma unroll
            for (int i = 0; i < 4; i++) {
                uint32_t off = (uint32_t)(m0 + i * 16 + ra) * 128 + (ks * 2 + ca) * 16;
                uint32_t sw = SW128(off);
                LDSM_X4(ah[4 * i], ah[4 * i + 1], ah[4 * i + 2], ah[4 * i + 3], aH + sw);
                LDSM_X4(al[4 * i], al[4 * i + 1], al[4 * i + 2], al[4 * i + 3], aL + sw);
            }
            uint32_t bh[8], bl[8];
#pragma unroll
            for (int jj = 0; jj < 2; jj++) {
                uint32_t off = (uint32_t)(n0 + (jj * 2 + (qb >> 1)) * 8 + l7) * 128
                             + (ks * 2 + (qb & 1)) * 16;
                uint32_t sw = SW128(off);
                LDSM_X4(bh[4 * jj], bh[4 * jj + 1], bh[4 * jj + 2], bh[4 * jj + 3], bH + sw);
                LDSM_X4(bl[4 * jj], bl[4 * jj + 1], bl[4 * jj + 2], bl[4 * jj + 3], bL + sw);
            }
#pragma unroll
            for (int i = 0; i < 4; i++)
#pragma unroll
                for (int j = 0; j < 4; j++) {
                    MMA_BF16(acc[i][j], &ah[4 * i], &bh[2 * j]);
                    MMA_BF16(acc[i][j], &ah[4 * i], &bl[2 * j]);
                    MMA_BF16(acc[i][j], &al[4 * i], &bh[2 * j]);
                }
        }
        __syncthreads();
    }
}

// ---------------------------------------------------------------------------
// QKV projections, one launch (grid.z = 0:Q, 1:K, 2:V).
// Epilogue writes attention-ready bf16 hi/lo layouts directly:
//   Q: head-major [bh][s][64], pre-scaled by 1/8
//   K: head-major [bh][s][64]
//   V: transposed  [bh][d][s]
// ---------------------------------------------------------------------------
__global__ __launch_bounds__(256, 1)
void gemm_qkv(const __nv_bfloat16* __restrict__ Ahi, const __nv_bfloat16* __restrict__ Alo,
              const __nv_bfloat16* __restrict__ Whi, const __nv_bfloat16* __restrict__ Wlo,
              __nv_bfloat16* __restrict__ qh, __nv_bfloat16* __restrict__ ql,
              __nv_bfloat16* __restrict__ kh, __nv_bfloat16* __restrict__ kl,
              __nv_bfloat16* __restrict__ vth, __nv_bfloat16* __restrict__ vtl)
{
    extern __shared__ char smem[];
    const uint32_t sbase = smem_to_u32(smem);
    const int tid = threadIdx.x;
    const int wid = tid >> 5, lane = tid & 31;
    const int bm = blockIdx.y * 128;
    const int bn = blockIdx.x * 128;
    const int z  = blockIdx.z;
    const int m0 = (wid & 1) * 64;
    const int n0 = (wid >> 1) * 32;

    float acc[4][4][4];
    gemm_mainloop(sbase, tid, wid, lane, m0, n0,
                  Ahi + (size_t)bm * D_MODEL,
                  Alo + (size_t)bm * D_MODEL,
                  Whi + (size_t)z * D_MODEL * D_MODEL + (size_t)bn * D_MODEL,
                  Wlo + (size_t)z * D_MODEL * D_MODEL + (size_t)bn * D_MODEL,
                  acc);

    const int g = lane >> 2, t = lane & 3;

    if (z == 2) {
        // V: transposed scattered bf16 writes
#pragma unroll
        for (int i = 0; i < 4; i++) {
#pragma unroll
            for (int j = 0; j < 4; j++) {
                const int c  = bn + n0 + j * 8 + 2 * t;
                const int hh = c >> 6, d0 = c & 63;
#pragma unroll
                for (int rr = 0; rr < 4; rr++) {
                    const int row = bm + m0 + i * 16 + g + ((rr >> 1) * 8);
                    const int b = row >> 11, s = row & (SEQ - 1);
                    const int d = d0 + (rr & 1);
                    float v = acc[i][j][rr];
                    __nv_bfloat16 hv = __float2bfloat16(v);
                    __nv_bfloat16 lv = __float2bfloat16(v - __bfloat162float(hv));
                    const size_t dst = ((size_t)((b * NHEAD + hh) * DK + d)) * SEQ + s;
                    vth[dst] = hv;
                    vtl[dst] = lv;
                }
            }
        }
    } else {
        __nv_bfloat16* Hi = (z == 0) ? qh : kh;
        __nv_bfloat16* Lo = (z == 0) ? ql : kl;
        const float sc = (z == 0) ? 0.125f : 1.0f;
#pragma unroll
        for (int i = 0; i < 4; i++) {
#pragma unroll
            for (int j = 0; j < 4; j++) {
                const int c  = bn + n0 + j * 8 + 2 * t;
                const int hh = c >> 6, d = c & 63;
                const int row0 = bm + m0 + i * 16 + g;
                uint32_t hv, lv;
                {
                    const int b = row0 >> 11, s = row0 & (SEQ - 1);
                    split2(acc[i][j][0] * sc, acc[i][j][1] * sc, hv, lv);
                    const size_t dst = ((size_t)((b * NHEAD + hh) * SEQ + s)) * DK + d;
                    *(uint32_t*)(Hi + dst) = hv;
                    *(uint32_t*)(Lo + dst) = lv;
                }
                {
                    const int row1 = row0 + 8;
                    const int b = row1 >> 11, s = row1 & (SEQ - 1);
                    split2(acc[i][j][2] * sc, acc[i][j][3] * sc, hv, lv);
                    const size_t dst = ((size_t)((b * NHEAD + hh) * SEQ + s)) * DK + d;
                    *(uint32_t*)(Hi + dst) = hv;
                    *(uint32_t*)(Lo + dst) = lv;
                }
            }
        }
    }
}

// ---------------------------------------------------------------------------
// Output projection GEMM (fp32 result to d_out)
// ---------------------------------------------------------------------------
__global__ __launch_bounds__(256, 1)
void gemm_mma(const __nv_bfloat16* __restrict__ Ahi, const __nv_bfloat16* __restrict__ Alo,
              const __nv_bfloat16* __restrict__ Bhi, const __nv_bfloat16* __restrict__ Blo,
              float* __restrict__ C)
{
    extern __shared__ char smem[];
    const uint32_t sbase = smem_to_u32(smem);
    const int tid = threadIdx.x;
    const int wid = tid >> 5, lane = tid & 31;
    const int bm = blockIdx.y * 128;
    const int bn = blockIdx.x * 128;
    const int m0 = (wid & 1) * 64;
    const int n0 = (wid >> 1) * 32;

    float acc[4][4][4];
    gemm_mainloop(sbase, tid, wid, lane, m0, n0,
                  Ahi + (size_t)bm * D_MODEL,
                  Alo + (size_t)bm * D_MODEL,
                  Bhi + (size_t)bn * D_MODEL,
                  Blo + (size_t)bn * D_MODEL,
                  acc);

    const int g = lane >> 2, t = lane & 3;
#pragma unroll
    for (int i = 0; i < 4; i++) {
#pragma unroll
        for (int j = 0; j < 4; j++) {
            float* cp0 = C + (size_t)(bm + m0 + i * 16 + g) * D_MODEL + bn + n0 + j * 8 + 2 * t;
            float* cp1 = cp0 + 8 * D_MODEL;
            *(float2*)cp0 = make_float2(acc[i][j][0], acc[i][j][1]);
            *(float2*)cp1 = make_float2(acc[i][j][2], acc[i][j][3]);
        }
    }
}

// ---------------------------------------------------------------------------
// Tensor-core causal flash attention (validated R7)
// ---------------------------------------------------------------------------
#define ATT_SMEM (32768 + 2 * 32768)

__global__ __launch_bounds__(256, 1)
void attn_mma(const __nv_bfloat16* __restrict__ Qh, const __nv_bfloat16* __restrict__ Ql,
              const __nv_bfloat16* __restrict__ Kh, const __nv_bfloat16* __restrict__ Kl,
              const __nv_bfloat16* __restrict__ Vh, const __nv_bfloat16* __restrict__ Vl,
              __nv_bfloat16* __restrict__ Ohi, __nv_bfloat16* __restrict__ Olo)
{
    extern __shared__ char smem[];
    const uint32_t sb = smem_to_u32(smem);
    const int tid = threadIdx.x, wid = tid >> 5, lane = tid & 31;
    const int qblk = gridDim.x - 1 - blockIdx.x;   // heavy CTAs first
    const int bh = blockIdx.y;
    const int b = bh >> 4, h = bh & 15;
    const int qr0 = qblk * 128 + wid * 16;
    const int g = lane >> 2, t = lane & 3;
    const int qb2 = lane >> 3, l7 = lane & 7;
    const int ra = lane & 15, ca = lane >> 4;

    const uint32_t QH = sb, QL = sb + 16384;
    const uint32_t BUF0 = sb + 32768;

    {
        const __nv_bfloat16* qh_g = Qh + ((size_t)bh * SEQ + qblk * 128) * DK;
        const __nv_bfloat16* ql_g = Ql + ((size_t)bh * SEQ + qblk * 128) * DK;
#pragma unroll
        for (int u = tid; u < 1024; u += 256) {
            int row = u >> 3, c = u & 7;
            uint32_t sw = SW128((uint32_t)(row * 128 + c * 16));
            CP_ASYNC16(QH + sw, qh_g + (size_t)row * DK + c * 8);
            CP_ASYNC16(QL + sw, ql_g + (size_t)row * DK + c * 8);
        }
        CP_COMMIT();
    }

    const int nkb = 2 * (qblk + 1);

    auto load_kv = [&](uint32_t dbuf, int k0) {
#pragma unroll
        for (int u = tid; u < 512; u += 256) {
            int r = u >> 3, c = u & 7;
            uint32_t sw = SW128((uint32_t)(r * 128 + c * 16));
            const size_t kg = ((size_t)bh * SEQ + k0 + r) * DK + c * 8;
            CP_ASYNC16(dbuf + sw,         Kh + kg);
            CP_ASYNC16(dbuf + 8192 + sw,  Kl + kg);
            const size_t vg = ((size_t)bh * DK + r) * SEQ + k0 + c * 8;
            CP_ASYNC16(dbuf + 16384 + sw, Vh + vg);
            CP_ASYNC16(dbuf + 24576 + sw, Vl + vg);
        }
    };

    load_kv(BUF0, 0);
    CP_COMMIT();

    CP_WAIT(1);
    __syncthreads();

    uint32_t qhf[16], qlf[16];
#pragma unroll
    for (int ks = 0; ks < 4; ks++) {
        uint32_t sw = SW128((uint32_t)((wid * 16 + ra) * 128 + (ks * 2 + ca) * 16));
        LDSM_X4(qhf[4 * ks], qhf[4 * ks + 1], qhf[4 * ks + 2], qhf[4 * ks + 3], QH + sw);
        LDSM_X4(qlf[4 * ks], qlf[4 * ks + 1], qlf[4 * ks + 2], qlf[4 * ks + 3], QL + sw);
    }

    float o[8][4];
#pragma unroll
    for (int j = 0; j < 8; j++)
#pragma unroll
        for (int r = 0; r < 4; r++) o[j][r] = 0.f;
    float m0 = NEG_INF, m1 = NEG_INF, l0 = 0.f, l1 = 0.f;

    for (int kb = 0; kb < nkb; kb++) {
        const int k0 = kb * 64;
        const int buf = kb & 1;
        if (kb + 1 < nkb) {
            load_kv(BUF0 + (buf ^ 1) * 32768, (kb + 1) * 64);
            CP_COMMIT();
            CP_WAIT(1);
        } else {
            CP_WAIT(0);
        }
        __syncthreads();

        if (k0 <= qr0 + 15) {
            const uint32_t KHs = BUF0 + buf * 32768;
            const uint32_t KLs = KHs + 8192;
            const uint32_t VHs = KHs + 16384;
            const uint32_t VLs = KHs + 24576;

            float sf[8][4];
#pragma unroll
            for (int j = 0; j < 8; j++)
#pragma unroll
                for (int r = 0; r < 4; r++) sf[j][r] = 0.f;

#pragma unroll
            for (int ks = 0; ks < 4; ks++) {
                uint32_t bhf[16], blf[16];
#pragma unroll
                for (int jj = 0; jj < 4; jj++) {
                    uint32_t sw = SW128((uint32_t)(((jj * 2 + (qb2 >> 1)) * 8 + l7) * 128
                                                   + (ks * 2 + (qb2 & 1)) * 16));
                    LDSM_X4(bhf[4 * jj], bhf[4 * jj + 1], bhf[4 * jj + 2], bhf[4 * jj + 3], KHs + sw);
                    LDSM_X4(blf[4 * jj], blf[4 * jj + 1], blf[4 * jj + 2], blf[4 * jj + 3], KLs + sw);
                }
#pragma unroll
                for (int j = 0; j < 8; j++) {
                    MMA_BF16(sf[j], &qhf[4 * ks], &bhf[2 * j]);
                    MMA_BF16(sf[j], &qhf[4 * ks], &blf[2 * j]);
                    MMA_BF16(sf[j], &qlf[4 * ks], &bhf[2 * j]);
                }
            }

            if (k0 + 63 > qr0) {
                const int row0 = qr0 + g, row1 = row0 + 8;
#pragma unroll
                for (int j = 0; j < 8; j++) {
                    const int key = k0 + 8 * j + 2 * t;
                    if (key     > row0) sf[j][0] = NEG_INF;
                    if (key + 1 > row0) sf[j][1] = NEG_INF;
                    if (key     > row1) sf[j][2] = NEG_INF;
                    if (key + 1 > row1) sf[j][3] = NEG_INF;
                }
            }

            float mx0 = NEG_INF, mx1 = NEG_INF;
#pragma unroll
            for (int j = 0; j < 8; j++) {
                mx0 = fmaxf(mx0, fmaxf(sf[j][0], sf[j][1]));
                mx1 = fmaxf(mx1, fmaxf(sf[j][2], sf[j][3]));
            }
            mx0 = fmaxf(mx0, __shfl_xor_sync(0xffffffffu, mx0, 1));
            mx0 = fmaxf(mx0, __shfl_xor_sync(0xffffffffu, mx0, 2));
            mx1 = fmaxf(mx1, __shfl_xor_sync(0xffffffffu, mx1, 1));
            mx1 = fmaxf(mx1, __shfl_xor_sync(0xffffffffu, mx1, 2));
            const float mn0 = fmaxf(m0, mx0), mn1 = fmaxf(m1, mx1);
            const float a0 = __expf(m0 - mn0), a1 = __expf(m1 - mn1);
            m0 = mn0; m1 = mn1;

            float rs0 = 0.f, rs1 = 0.f;
            uint32_t ph[16], pl[16];
#pragma unroll
            for (int j = 0; j < 8; j++) {
                float p0 = __expf(sf[j][0] - mn0);
                float p1 = __expf(sf[j][1] - mn0);
                float p2 = __expf(sf[j][2] - mn1);
                float p3 = __expf(sf[j][3] - mn1);
                rs0 += p0 + p1;
                rs1 += p2 + p3;
                const int ks2 = j >> 1, hf = j & 1;
                split2(p0, p1, ph[4 * ks2 + 2 * hf],     pl[4 * ks2 + 2 * hf]);
                split2(p2, p3, ph[4 * ks2 + 2 * hf + 1], pl[4 * ks2 + 2 * hf + 1]);
            }
            rs0 += __shfl_xor_sync(0xffffffffu, rs0, 1);
            rs0 += __shfl_xor_sync(0xffffffffu, rs0, 2);
            rs1 += __shfl_xor_sync(0xffffffffu, rs1, 1);
            rs1 += __shfl_xor_sync(0xffffffffu, rs1, 2);
            l0 = l0 * a0 + rs0;
            l1 = l1 * a1 + rs1;

#pragma unroll
            for (int j = 0; j < 8; j++) {
                o[j][0] *= a0; o[j][1] *= a0;
                o[j][2] *= a1; o[j][3] *= a1;
            }

#pragma unroll
            for (int ks = 0; ks < 4; ks++) {
                uint32_t vhf[16], vlf[16];
#pragma unroll
                for (int jj = 0; jj < 4; jj++) {
                    uint32_t sw = SW128((uint32_t)(((jj * 2 + (qb2 >> 1)) * 8 + l7) * 128
                                                   + (ks * 2 + (qb2 & 1)) * 16));
                    LDSM_X4(vhf[4 * jj], vhf[4 * jj + 1], vhf[4 * jj + 2], vhf[4 * jj + 3], VHs + sw);
                    LDSM_X4(vlf[4 * jj], vlf[4 * jj + 1], vlf[4 * jj + 2], vlf[4 * jj + 3], VLs + sw);
                }
#pragma unroll
                for (int j = 0; j < 8; j++) {
                    MMA_BF16(o[j], &ph[4 * ks], &vhf[2 * j]);
                    MMA_BF16(o[j], &ph[4 * ks], &vlf[2 * j]);
                    MMA_BF16(o[j], &pl[4 * ks], &vhf[2 * j]);
                }
            }
        }
        __syncthreads();
    }

    const float il0 = 1.f / l0, il1 = 1.f / l1;
    const size_t r0 = (size_t)(b * SEQ + qr0 + g) * D_MODEL + h * DK;
    const size_t r1 = r0 + (size_t)8 * D_MODEL;
#pragma unroll
    for (int j = 0; j < 8; j++) {
        const int c = 8 * j + 2 * t;
        uint32_t hv, lv;
        split2(o[j][0] * il0, o[j][1] * il0, hv, lv);
        *(uint32_t*)(Ohi + r0 + c) = hv;
        *(uint32_t*)(Olo + r0 + c) = lv;
        split2(o[j][2] * il1, o[j][3] * il1, hv, lv);
        *(uint32_t*)(Ohi + r1 + c) = hv;
        *(uint32_t*)(Olo + r1 + c) = lv;
    }
}

// ---------------------------------------------------------------------------
extern "C" void kernel_launch(void* const* d_in, const int* in_sizes, int n_in,
                              void* d_out, int out_size)
{
    (void)in_sizes; (void)n_in; (void)out_size;
    const float* x  = (const float*)d_in[0];
    const float* Wq = (const float*)d_in[1];
    const float* Wk = (const float*)d_in[2];
    const float* Wv = (const float*)d_in[3];
    const float* Wo = (const float*)d_in[4];
    float* out = (float*)d_out;

    __nv_bfloat16 *xhi, *xlo, *ohi, *olo, *whi, *wlo;
    cudaGetSymbolAddress((void**)&xhi, g_x_hi);
    cudaGetSymbolAddress((void**)&xlo, g_x_lo);
    cudaGetSymbolAddress((void**)&ohi, g_o_hi);
    cudaGetSymbolAddress((void**)&olo, g_o_lo);
    cudaGetSymbolAddress((void**)&whi, g_w_hi);
    cudaGetSymbolAddress((void**)&wlo, g_w_lo);
    __nv_bfloat16 *qh, *ql, *kh, *kl, *vth, *vtl;
    cudaGetSymbolAddress((void**)&qh,  g_qh);
    cudaGetSymbolAddress((void**)&ql,  g_ql);
    cudaGetSymbolAddress((void**)&kh,  g_kh);
    cudaGetSymbolAddress((void**)&kl,  g_kl);
    cudaGetSymbolAddress((void**)&vth, g_vth);
    cudaGetSymbolAddress((void**)&vtl, g_vtl);

    cudaFuncSetAttribute(gemm_qkv, cudaFuncAttributeMaxDynamicSharedMemorySize, GEMM_SMEM);
    cudaFuncSetAttribute(gemm_mma, cudaFuncAttributeMaxDynamicSharedMemorySize, GEMM_SMEM);
    cudaFuncSetAttribute(attn_mma, cudaFuncAttributeMaxDynamicSharedMemorySize, ATT_SMEM);

    const int NX4 = MTOT * D_MODEL / 4;      // 1,048,576
    const int NW4 = D_MODEL * D_MODEL / 4;   // 262,144
    const int WSZ = D_MODEL * D_MODEL;

    cvt_split<<<NX4 / 256, 256>>>(x, xhi, xlo, NX4);
    cvt_w4<<<dim3(NW4 / 256, 4), 256>>>(Wq, Wk, Wv, Wo, whi, wlo, NW4);

    // W order in g_w: [0]=Wq, [1]=Wk, [2]=Wv, [3]=Wo ; gemm_qkv uses z = 0..2
    gemm_qkv<<<dim3(D_MODEL / 128, MTOT / 128, 3), 256, GEMM_SMEM>>>(
        xhi, xlo, whi, wlo, qh, ql, kh, kl, vth, vtl);

    attn_mma<<<dim3(SEQ / 128, BH), 256, ATT_SMEM>>>(qh, ql, kh, kl, vth, vtl, ohi, olo);

    gemm_mma<<<dim3(D_MODEL / 128, MTOT / 128), 256, GEMM_SMEM>>>(
        ohi, olo, whi + 3 * WSZ, wlo + 3 * WSZ, out);
}